// round 1
// baseline (speedup 1.0000x reference)
#include <cuda_runtime.h>

// Problem constants
#define T_DIM 2048
#define B_DIM 2
#define E_DIM 1024
#define H_DIM 16
#define DH    64
#define TB    (T_DIM * B_DIM)   // 4096 rows
#define E3    (3 * E_DIM)       // 3072

// Scratch (device globals; no runtime allocation allowed)
__device__ float g_Q[B_DIM * H_DIM * T_DIM * DH];   // 16 MB, layout [B*H][T][DH], pre-scaled
__device__ float g_K[B_DIM * H_DIM * T_DIM * DH];   // 16 MB
__device__ float g_V[B_DIM * H_DIM * T_DIM * DH];   // 16 MB
__device__ float g_attn[TB * E_DIM];                // 16 MB, [t*B+b][E]

// ---------------------------------------------------------------------------
// Kernel 1: fused QKV projection.
// C[r][f] = dot(X[r][:], W[f][:]) + bias[f], r in [0,4096), f in [0,3072)
// X = query [T,B,E] row-major -> [4096][1024]; W = in_proj_weight [3072][1024]
// Scatter into g_Q (scaled by DH^-0.5 = 0.125), g_K, g_V as [B*H][T][DH].
// 128x128x16 tile, 256 threads, 8x8 microkernel (split 4+4 registers).
// ---------------------------------------------------------------------------
__global__ __launch_bounds__(256) void qkv_gemm_kernel(
    const float* __restrict__ X, const float* __restrict__ W,
    const float* __restrict__ bias)
{
    __shared__ float As[16][128];
    __shared__ float Bs[16][128];

    const int tid = threadIdx.x;
    const int ty = tid >> 4;        // 0..15
    const int tx = tid & 15;        // 0..15
    const int rowBase = blockIdx.y * 128;
    const int colBase = blockIdx.x * 128;

    // load mapping: each thread loads 2 float4 from A and 2 from B per K-tile
    const int lRow = tid >> 2;          // 0..63
    const int lK   = (tid & 3) << 2;    // 0,4,8,12

    float acc[8][8];
#pragma unroll
    for (int i = 0; i < 8; i++)
#pragma unroll
        for (int j = 0; j < 8; j++) acc[i][j] = 0.0f;

    for (int k0 = 0; k0 < E_DIM; k0 += 16) {
#pragma unroll
        for (int s = 0; s < 2; s++) {
            int r = lRow + s * 64;
            float4 v = *reinterpret_cast<const float4*>(
                &X[(size_t)(rowBase + r) * E_DIM + k0 + lK]);
            As[lK + 0][r] = v.x; As[lK + 1][r] = v.y;
            As[lK + 2][r] = v.z; As[lK + 3][r] = v.w;
        }
#pragma unroll
        for (int s = 0; s < 2; s++) {
            int c = lRow + s * 64;
            float4 v = *reinterpret_cast<const float4*>(
                &W[(size_t)(colBase + c) * E_DIM + k0 + lK]);
            Bs[lK + 0][c] = v.x; Bs[lK + 1][c] = v.y;
            Bs[lK + 2][c] = v.z; Bs[lK + 3][c] = v.w;
        }
        __syncthreads();

#pragma unroll
        for (int k = 0; k < 16; k++) {
            float a[8], b[8];
            *reinterpret_cast<float4*>(&a[0]) = *reinterpret_cast<float4*>(&As[k][ty * 4]);
            *reinterpret_cast<float4*>(&a[4]) = *reinterpret_cast<float4*>(&As[k][64 + ty * 4]);
            *reinterpret_cast<float4*>(&b[0]) = *reinterpret_cast<float4*>(&Bs[k][tx * 4]);
            *reinterpret_cast<float4*>(&b[4]) = *reinterpret_cast<float4*>(&Bs[k][64 + tx * 4]);
#pragma unroll
            for (int i = 0; i < 8; i++)
#pragma unroll
                for (int j = 0; j < 8; j++)
                    acc[i][j] += a[i] * b[j];
        }
        __syncthreads();
    }

    // Epilogue: add bias, scale Q, scatter to [B*H][T][DH]
#pragma unroll
    for (int i = 0; i < 8; i++) {
        int r = rowBase + ((i < 4) ? (ty * 4 + i) : (64 + ty * 4 + (i - 4)));
        int t = r >> 1;         // r = t*B + b, B=2
        int bb = r & 1;
#pragma unroll
        for (int j = 0; j < 8; j++) {
            int f = colBase + ((j < 4) ? (tx * 4 + j) : (64 + tx * 4 + (j - 4)));
            float v = acc[i][j] + bias[f];
            int which = f >> 10;        // f / 1024
            int rem = f & 1023;
            int h = rem >> 6;           // / 64
            int d = rem & 63;
            int idx = ((bb * H_DIM + h) * T_DIM + t) * DH + d;
            if (which == 0)      g_Q[idx] = v * 0.125f;   // DH^-0.5
            else if (which == 1) g_K[idx] = v;
            else                 g_V[idx] = v;
        }
    }
}

// ---------------------------------------------------------------------------
// Kernel 2: flash attention, fp32.
// grid = (B*H=32, T/64=32), 256 threads.
// BM=64 queries, BN=64 keys per iteration. Thread (ty,tx) in 16x16:
//   rows  r0+i   = ty*4 + i         (i=0..3)
//   cols  c(j)   = tx + 16*j        (j=0..3)  [scores]  / dims for O
// K smem buffer (pitch 68 floats) is reused to hold P between phases.
// ---------------------------------------------------------------------------
#define KPITCH 68

__global__ __launch_bounds__(256) void flash_attn_kernel()
{
    extern __shared__ float smem[];
    float* Qs = smem;                       // [64][64]
    float* Ks = smem + 64 * 64;             // [64][KPITCH] (also Ps)
    float* Vs = Ks + 64 * KPITCH;           // [64][64]

    const int tid = threadIdx.x;
    const int ty = tid >> 4;
    const int tx = tid & 15;
    const int bh = blockIdx.x;              // b*H + h
    const int q0 = blockIdx.y * 64;

    const float* Qg = g_Q + (size_t)bh * T_DIM * DH;
    const float* Kg = g_K + (size_t)bh * T_DIM * DH;
    const float* Vg = g_V + (size_t)bh * T_DIM * DH;

    // Load Q tile (64x64) coalesced
#pragma unroll
    for (int s = 0; s < 4; s++) {
        int e = (tid + s * 256) * 4;
        int r = e >> 6, d = e & 63;
        *reinterpret_cast<float4*>(&Qs[r * 64 + d]) =
            *reinterpret_cast<const float4*>(&Qg[(size_t)(q0 + r) * DH + d]);
    }

    float acc[4][4];
    float m_i[4], l_i[4];
#pragma unroll
    for (int i = 0; i < 4; i++) {
        m_i[i] = -1e30f; l_i[i] = 0.0f;
#pragma unroll
        for (int j = 0; j < 4; j++) acc[i][j] = 0.0f;
    }

    const int r0 = ty * 4;

    for (int kt = 0; kt < T_DIM; kt += 64) {
        __syncthreads();   // previous iteration's Ps/Vs reads complete
        // Load K tile -> Ks (pitch 68), V tile -> Vs (pitch 64)
#pragma unroll
        for (int s = 0; s < 4; s++) {
            int e = (tid + s * 256) * 4;
            int r = e >> 6, d = e & 63;
            *reinterpret_cast<float4*>(&Ks[r * KPITCH + d]) =
                *reinterpret_cast<const float4*>(&Kg[(size_t)(kt + r) * DH + d]);
            *reinterpret_cast<float4*>(&Vs[r * 64 + d]) =
                *reinterpret_cast<const float4*>(&Vg[(size_t)(kt + r) * DH + d]);
        }
        __syncthreads();

        // S = Q K^T (Q pre-scaled)
        float s4[4][4];
#pragma unroll
        for (int i = 0; i < 4; i++)
#pragma unroll
            for (int j = 0; j < 4; j++) s4[i][j] = 0.0f;

#pragma unroll
        for (int d = 0; d < 64; d += 4) {
            float4 q4[4], k4[4];
#pragma unroll
            for (int i = 0; i < 4; i++)
                q4[i] = *reinterpret_cast<float4*>(&Qs[(r0 + i) * 64 + d]);
#pragma unroll
            for (int j = 0; j < 4; j++)
                k4[j] = *reinterpret_cast<float4*>(&Ks[(tx + j * 16) * KPITCH + d]);
#pragma unroll
            for (int i = 0; i < 4; i++)
#pragma unroll
                for (int j = 0; j < 4; j++) {
                    s4[i][j] += q4[i].x * k4[j].x;
                    s4[i][j] += q4[i].y * k4[j].y;
                    s4[i][j] += q4[i].z * k4[j].z;
                    s4[i][j] += q4[i].w * k4[j].w;
                }
        }

        // Online softmax per row (row shared by the 16 tx-lanes of this ty)
#pragma unroll
        for (int i = 0; i < 4; i++) {
            float mx = fmaxf(fmaxf(s4[i][0], s4[i][1]), fmaxf(s4[i][2], s4[i][3]));
#pragma unroll
            for (int o = 8; o >= 1; o >>= 1)
                mx = fmaxf(mx, __shfl_xor_sync(0xffffffffu, mx, o));
            float m_new = fmaxf(m_i[i], mx);
            float corr = __expf(m_i[i] - m_new);
            float lsum = 0.0f;
#pragma unroll
            for (int j = 0; j < 4; j++) {
                s4[i][j] = __expf(s4[i][j] - m_new);
                lsum += s4[i][j];
            }
#pragma unroll
            for (int o = 8; o >= 1; o >>= 1)
                lsum += __shfl_xor_sync(0xffffffffu, lsum, o);
            l_i[i] = l_i[i] * corr + lsum;
            m_i[i] = m_new;
#pragma unroll
            for (int j = 0; j < 4; j++) acc[i][j] *= corr;
        }

        __syncthreads();   // all lanes done reading Ks
        // Write P into the K buffer
#pragma unroll
        for (int i = 0; i < 4; i++)
#pragma unroll
            for (int j = 0; j < 4; j++)
                Ks[(r0 + i) * KPITCH + tx + j * 16] = s4[i][j];
        __syncthreads();

        // acc += P @ V
#pragma unroll
        for (int c = 0; c < 64; c += 4) {
            float pr[4][4];
#pragma unroll
            for (int i = 0; i < 4; i++) {
                float4 p4 = *reinterpret_cast<float4*>(&Ks[(r0 + i) * KPITCH + c]);
                pr[i][0] = p4.x; pr[i][1] = p4.y; pr[i][2] = p4.z; pr[i][3] = p4.w;
            }
#pragma unroll
            for (int cc = 0; cc < 4; cc++) {
                float vv[4];
#pragma unroll
                for (int jj = 0; jj < 4; jj++)
                    vv[jj] = Vs[(c + cc) * 64 + tx + jj * 16];
#pragma unroll
                for (int i = 0; i < 4; i++)
#pragma unroll
                    for (int jj = 0; jj < 4; jj++)
                        acc[i][jj] += pr[i][cc] * vv[jj];
            }
        }
    }

    // Epilogue: normalize, write to g_attn as [t*B+b][h*DH+d]
    const int b = bh >> 4;
    const int h = bh & 15;
#pragma unroll
    for (int i = 0; i < 4; i++) {
        int t = q0 + r0 + i;
        float inv = 1.0f / l_i[i];
#pragma unroll
        for (int jj = 0; jj < 4; jj++) {
            int d = tx + jj * 16;
            g_attn[((size_t)t * B_DIM + b) * E_DIM + h * DH + d] = acc[i][jj] * inv;
        }
    }
}

// ---------------------------------------------------------------------------
// Kernel 3: output projection.
// out[r][o] = dot(g_attn[r][:], out_w[o][:]) + out_b[o]
// Same 128x128x16 microkernel. out is [T,B,E] row-major = [4096][1024].
// ---------------------------------------------------------------------------
__global__ __launch_bounds__(256) void out_gemm_kernel(
    const float* __restrict__ W, const float* __restrict__ bias,
    float* __restrict__ out)
{
    __shared__ float As[16][128];
    __shared__ float Bs[16][128];

    const int tid = threadIdx.x;
    const int ty = tid >> 4;
    const int tx = tid & 15;
    const int rowBase = blockIdx.y * 128;
    const int colBase = blockIdx.x * 128;

    const int lRow = tid >> 2;
    const int lK   = (tid & 3) << 2;

    float acc[8][8];
#pragma unroll
    for (int i = 0; i < 8; i++)
#pragma unroll
        for (int j = 0; j < 8; j++) acc[i][j] = 0.0f;

    for (int k0 = 0; k0 < E_DIM; k0 += 16) {
#pragma unroll
        for (int s = 0; s < 2; s++) {
            int r = lRow + s * 64;
            float4 v = *reinterpret_cast<const float4*>(
                &g_attn[(size_t)(rowBase + r) * E_DIM + k0 + lK]);
            As[lK + 0][r] = v.x; As[lK + 1][r] = v.y;
            As[lK + 2][r] = v.z; As[lK + 3][r] = v.w;
        }
#pragma unroll
        for (int s = 0; s < 2; s++) {
            int c = lRow + s * 64;
            float4 v = *reinterpret_cast<const float4*>(
                &W[(size_t)(colBase + c) * E_DIM + k0 + lK]);
            Bs[lK + 0][c] = v.x; Bs[lK + 1][c] = v.y;
            Bs[lK + 2][c] = v.z; Bs[lK + 3][c] = v.w;
        }
        __syncthreads();

#pragma unroll
        for (int k = 0; k < 16; k++) {
            float a[8], b[8];
            *reinterpret_cast<float4*>(&a[0]) = *reinterpret_cast<float4*>(&As[k][ty * 4]);
            *reinterpret_cast<float4*>(&a[4]) = *reinterpret_cast<float4*>(&As[k][64 + ty * 4]);
            *reinterpret_cast<float4*>(&b[0]) = *reinterpret_cast<float4*>(&Bs[k][tx * 4]);
            *reinterpret_cast<float4*>(&b[4]) = *reinterpret_cast<float4*>(&Bs[k][64 + tx * 4]);
#pragma unroll
            for (int i = 0; i < 8; i++)
#pragma unroll
                for (int j = 0; j < 8; j++)
                    acc[i][j] += a[i] * b[j];
        }
        __syncthreads();
    }

#pragma unroll
    for (int i = 0; i < 8; i++) {
        int r = rowBase + ((i < 4) ? (ty * 4 + i) : (64 + ty * 4 + (i - 4)));
#pragma unroll
        for (int j = 0; j < 8; j++) {
            int f = colBase + ((j < 4) ? (tx * 4 + j) : (64 + tx * 4 + (j - 4)));
            out[(size_t)r * E_DIM + f] = acc[i][j] + bias[f];
        }
    }
}

// ---------------------------------------------------------------------------
// Launch
// inputs: 0=query [T,B,E], 1=key(unused), 2=value(unused),
//         3=in_proj_weight [3E,E], 4=in_proj_bias [3E],
//         5=out_w [E,E], 6=out_b [E]
// ---------------------------------------------------------------------------
extern "C" void kernel_launch(void* const* d_in, const int* in_sizes, int n_in,
                              void* d_out, int out_size)
{
    const float* query = (const float*)d_in[0];
    const float* in_w  = (const float*)d_in[3];
    const float* in_b  = (const float*)d_in[4];
    const float* out_w = (const float*)d_in[5];
    const float* out_b = (const float*)d_in[6];
    float* out = (float*)d_out;

    // 1) QKV projection: C[4096][3072]
    qkv_gemm_kernel<<<dim3(E3 / 128, TB / 128), 256>>>(query, in_w, in_b);

    // 2) Flash attention
    const int smem_bytes = (64 * 64 + 64 * KPITCH + 64 * 64) * (int)sizeof(float); // 50176
    cudaFuncSetAttribute(flash_attn_kernel,
                         cudaFuncAttributeMaxDynamicSharedMemorySize, smem_bytes);
    flash_attn_kernel<<<dim3(B_DIM * H_DIM, T_DIM / 64), 256, smem_bytes>>>();

    // 3) Output projection: out[4096][1024]
    out_gemm_kernel<<<dim3(E_DIM / 128, TB / 128), 256>>>(out_w, out_b, out);
}

// round 3
// speedup vs baseline: 1.3279x; 1.3279x over previous
#include <cuda_runtime.h>
#include <cuda_bf16.h>
#include <cstdint>

// Problem constants
#define T_DIM 2048
#define B_DIM 2
#define E_DIM 1024
#define H_DIM 16
#define DH    64
#define TB    (T_DIM * B_DIM)   // 4096
#define E3    (3 * E_DIM)       // 3072

// ---------------------------------------------------------------------------
// Device scratch (no runtime allocation allowed)
// ---------------------------------------------------------------------------
__device__ float g_Q[B_DIM * H_DIM * T_DIM * DH];   // [B*H][T][DH], pre-scaled
__device__ float g_K[B_DIM * H_DIM * T_DIM * DH];
__device__ float g_V[B_DIM * H_DIM * T_DIM * DH];

__device__ __nv_bfloat16 g_Xhi[TB * E_DIM],  g_Xlo[TB * E_DIM];        // query split
__device__ __nv_bfloat16 g_Whi[E3 * E_DIM],  g_Wlo[E3 * E_DIM];        // in_proj_weight split
__device__ __nv_bfloat16 g_OWhi[E_DIM * E_DIM], g_OWlo[E_DIM * E_DIM]; // out_w split
__device__ __nv_bfloat16 g_Ahi[TB * E_DIM],  g_Alo[TB * E_DIM];        // attn output split

// ---------------------------------------------------------------------------
// HMMA helpers (base sm_103-legal PTX: ldmatrix + mma.sync)
// ---------------------------------------------------------------------------
__device__ __forceinline__ uint32_t smem_u32(const void* p) {
    uint32_t a;
    asm("{ .reg .u64 t; cvta.to.shared.u64 t, %1; cvt.u32.u64 %0, t; }" : "=r"(a) : "l"(p));
    return a;
}

__device__ __forceinline__ void ldsm_x4(uint32_t& r0, uint32_t& r1, uint32_t& r2,
                                        uint32_t& r3, uint32_t addr) {
    asm volatile("ldmatrix.sync.aligned.m8n8.x4.shared.b16 {%0,%1,%2,%3}, [%4];"
                 : "=r"(r0), "=r"(r1), "=r"(r2), "=r"(r3) : "r"(addr));
}

__device__ __forceinline__ void mma_bf16(float* d, const uint32_t* a, const uint32_t* b) {
    asm volatile(
        "mma.sync.aligned.m16n8k16.row.col.f32.bf16.bf16.f32 "
        "{%0,%1,%2,%3}, {%4,%5,%6,%7}, {%8,%9}, {%0,%1,%2,%3};"
        : "+f"(d[0]), "+f"(d[1]), "+f"(d[2]), "+f"(d[3])
        : "r"(a[0]), "r"(a[1]), "r"(a[2]), "r"(a[3]), "r"(b[0]), "r"(b[1]));
}

// ---------------------------------------------------------------------------
// Kernel 0: fp32 -> (bf16 hi, bf16 lo) split conversion, vectorized
// ---------------------------------------------------------------------------
__global__ __launch_bounds__(256) void cvt_split_kernel(
    const float* __restrict__ x, __nv_bfloat16* __restrict__ hi,
    __nv_bfloat16* __restrict__ lo, int n4)
{
    int i = blockIdx.x * blockDim.x + threadIdx.x;
    if (i >= n4) return;
    float4 v = reinterpret_cast<const float4*>(x)[i];
    __nv_bfloat16 h0 = __float2bfloat16(v.x), h1 = __float2bfloat16(v.y);
    __nv_bfloat16 h2 = __float2bfloat16(v.z), h3 = __float2bfloat16(v.w);
    __nv_bfloat16 l0 = __float2bfloat16(v.x - __bfloat162float(h0));
    __nv_bfloat16 l1 = __float2bfloat16(v.y - __bfloat162float(h1));
    __nv_bfloat16 l2 = __float2bfloat16(v.z - __bfloat162float(h2));
    __nv_bfloat16 l3 = __float2bfloat16(v.w - __bfloat162float(h3));
    __nv_bfloat162* hp = reinterpret_cast<__nv_bfloat162*>(hi);
    __nv_bfloat162* lp = reinterpret_cast<__nv_bfloat162*>(lo);
    hp[2 * i + 0] = __nv_bfloat162(h0, h1);
    hp[2 * i + 1] = __nv_bfloat162(h2, h3);
    lp[2 * i + 0] = __nv_bfloat162(l0, l1);
    lp[2 * i + 1] = __nv_bfloat162(l2, l3);
}

// ---------------------------------------------------------------------------
// HMMA split-bf16 GEMM. C[128x128 tile] = A * B^T, A:[M][1024], B:[N][1024] K-major.
// C = Ah*Bh + Ah*Bl + Al*Bh (fp32 accum).
// 256 threads = 8 warps in 4(M) x 2(N); warp tile 32x64 = 2 m16 x 8 n8.
// Smem: 4 staging buffers, 128 rows x 32 bf16 (64B) padded to 80B pitch
//       (80B = 20-bank rotation per row -> conflict-free ldmatrix).
// MODE 0: QKV -> scatter g_Q (*0.125), g_K, g_V.  MODE 1: out-proj -> d_out.
// ---------------------------------------------------------------------------
#define BK     32
#define PITCH  80
#define BUFSZ  (128 * PITCH)   // 10240

template<int MODE>
__global__ __launch_bounds__(256) void hmma_gemm_kernel(
    const __nv_bfloat16* __restrict__ Ahi, const __nv_bfloat16* __restrict__ Alo,
    const __nv_bfloat16* __restrict__ Bhi, const __nv_bfloat16* __restrict__ Blo,
    const float* __restrict__ bias, float* __restrict__ out)
{
    __shared__ char smem[4 * BUFSZ];
    char* sAh = smem;
    char* sAl = smem + BUFSZ;
    char* sBh = smem + 2 * BUFSZ;
    char* sBl = smem + 3 * BUFSZ;

    const int tid  = threadIdx.x;
    const int wid  = tid >> 5;
    const int lane = tid & 31;
    const int wm = wid & 3;        // 0..3 -> 32-row band
    const int wn = wid >> 2;       // 0..1 -> 64-col band
    const int rowBase = blockIdx.y * 128;
    const int colBase = blockIdx.x * 128;

    const uint32_t sb_Ah = smem_u32(sAh);
    const uint32_t sb_Al = smem_u32(sAl);
    const uint32_t sb_Bh = smem_u32(sBh);
    const uint32_t sb_Bl = smem_u32(sBl);

    float acc[2][8][4];
#pragma unroll
    for (int i = 0; i < 2; i++)
#pragma unroll
        for (int j = 0; j < 8; j++)
#pragma unroll
            for (int k = 0; k < 4; k++) acc[i][j][k] = 0.0f;

    // ldmatrix base addresses (lane-dependent parts)
    // A: row = band + (lane&15), k-half = lane>>4
    const uint32_t aoff = (uint32_t)((wm * 32 + (lane & 15)) * PITCH + (lane >> 4) * 16);
    // B: row = wn*64 + np*16 + (lane>>4)*8 + (lane&7), k-half = (lane>>3)&1
    const uint32_t boff = (uint32_t)((wn * 64 + (lane >> 4) * 8 + (lane & 7)) * PITCH +
                                     ((lane >> 3) & 1) * 16);

    for (int k0 = 0; k0 < E_DIM; k0 += BK) {
        __syncthreads();
        // Stage 4 tiles: 128 rows x 32 bf16 each. 512 uint4 per tile, 2/thread.
#pragma unroll
        for (int s = 0; s < 2; s++) {
            int unit = tid + s * 256;         // 0..511
            int row = unit >> 2, seg = unit & 3;
            uint32_t so = (uint32_t)(row * PITCH + seg * 16);
            size_t ao = (size_t)(rowBase + row) * E_DIM + k0 + seg * 8;
            size_t bo = (size_t)(colBase + row) * E_DIM + k0 + seg * 8;
            *reinterpret_cast<uint4*>(sAh + so) = *reinterpret_cast<const uint4*>(Ahi + ao);
            *reinterpret_cast<uint4*>(sAl + so) = *reinterpret_cast<const uint4*>(Alo + ao);
            *reinterpret_cast<uint4*>(sBh + so) = *reinterpret_cast<const uint4*>(Bhi + bo);
            *reinterpret_cast<uint4*>(sBl + so) = *reinterpret_cast<const uint4*>(Blo + bo);
        }
        __syncthreads();

#pragma unroll
        for (int ks = 0; ks < BK; ks += 16) {
            const uint32_t kb = (uint32_t)(ks * 2);  // byte offset along K
            uint32_t ah[2][4], al[2][4];
#pragma unroll
            for (int mt = 0; mt < 2; mt++) {
                uint32_t ar = aoff + (uint32_t)(mt * 16 * PITCH) + kb;
                ldsm_x4(ah[mt][0], ah[mt][1], ah[mt][2], ah[mt][3], sb_Ah + ar);
                ldsm_x4(al[mt][0], al[mt][1], al[mt][2], al[mt][3], sb_Al + ar);
            }
#pragma unroll
            for (int np = 0; np < 4; np++) {
                uint32_t br = boff + (uint32_t)(np * 16 * PITCH) + kb;
                uint32_t bh[4], bl[4];
                ldsm_x4(bh[0], bh[1], bh[2], bh[3], sb_Bh + br);
                ldsm_x4(bl[0], bl[1], bl[2], bl[3], sb_Bl + br);
#pragma unroll
                for (int mt = 0; mt < 2; mt++) {
#pragma unroll
                    for (int j = 0; j < 2; j++) {
                        float* d = acc[mt][np * 2 + j];
                        mma_bf16(d, ah[mt], &bh[j * 2]);   // hi*hi
                        mma_bf16(d, ah[mt], &bl[j * 2]);   // hi*lo
                        mma_bf16(d, al[mt], &bh[j * 2]);   // lo*hi
                    }
                }
            }
        }
    }

    // Epilogue. Thread owns: rows r = rowBase + wm*32 + mt*16 + lane/4 + {0,8},
    //                        cols c = colBase + wn*64 + nt*8 + (lane&3)*2 + {0,1}.
    const int rloc = wm * 32 + (lane >> 2);
    const int cloc = wn * 64 + (lane & 3) * 2;

    if (MODE == 0) {
        const int f0 = colBase + wn * 64;          // 64-aligned -> fixed head segment
        const int which = f0 >> 10;
        const int h = (f0 & 1023) >> 6;
        float* base;
        float scale;
        if (which == 0)      { base = g_Q; scale = 0.125f; }
        else if (which == 1) { base = g_K; scale = 1.0f; }
        else                 { base = g_V; scale = 1.0f; }
#pragma unroll
        for (int mt = 0; mt < 2; mt++) {
#pragma unroll
            for (int half = 0; half < 2; half++) {
                int r = rowBase + rloc + mt * 16 + half * 8;
                int t = r >> 1, bb = r & 1;
                float* dst = base + ((size_t)(bb * H_DIM + h) * T_DIM + t) * DH;
#pragma unroll
                for (int nt = 0; nt < 8; nt++) {
                    int d = (nt * 8) + (cloc & 63);
                    float2 v;
                    v.x = (acc[mt][nt][half * 2 + 0] + bias[f0 + d])     * scale;
                    v.y = (acc[mt][nt][half * 2 + 1] + bias[f0 + d + 1]) * scale;
                    *reinterpret_cast<float2*>(dst + d) = v;
                }
            }
        }
    } else {
#pragma unroll
        for (int mt = 0; mt < 2; mt++) {
#pragma unroll
            for (int half = 0; half < 2; half++) {
                int r = rowBase + rloc + mt * 16 + half * 8;
                float* dst = out + (size_t)r * E_DIM;
#pragma unroll
                for (int nt = 0; nt < 8; nt++) {
                    int c = colBase + wn * 64 + nt * 8 + (lane & 3) * 2;
                    float2 v;
                    v.x = acc[mt][nt][half * 2 + 0] + bias[c];
                    v.y = acc[mt][nt][half * 2 + 1] + bias[c + 1];
                    *reinterpret_cast<float2*>(dst + c) = v;
                }
            }
        }
    }
}

// ---------------------------------------------------------------------------
// Kernel 2: flash attention, fp32; epilogue emits bf16 hi/lo for out-proj
// ---------------------------------------------------------------------------
#define KPITCH 68

__global__ __launch_bounds__(256) void flash_attn_kernel()
{
    extern __shared__ float fsm[];
    float* Qs = fsm;                       // [64][64]
    float* Ks = fsm + 64 * 64;             // [64][KPITCH] (also Ps)
    float* Vs = Ks + 64 * KPITCH;          // [64][64]

    const int tid = threadIdx.x;
    const int ty = tid >> 4;
    const int tx = tid & 15;
    const int bh = blockIdx.x;             // b*H + h
    const int q0 = blockIdx.y * 64;

    const float* Qg = g_Q + (size_t)bh * T_DIM * DH;
    const float* Kg = g_K + (size_t)bh * T_DIM * DH;
    const float* Vg = g_V + (size_t)bh * T_DIM * DH;

#pragma unroll
    for (int s = 0; s < 4; s++) {
        int e = (tid + s * 256) * 4;
        int r = e >> 6, d = e & 63;
        *reinterpret_cast<float4*>(&Qs[r * 64 + d]) =
            *reinterpret_cast<const float4*>(&Qg[(size_t)(q0 + r) * DH + d]);
    }

    float acc[4][4];
    float m_i[4], l_i[4];
#pragma unroll
    for (int i = 0; i < 4; i++) {
        m_i[i] = -1e30f; l_i[i] = 0.0f;
#pragma unroll
        for (int j = 0; j < 4; j++) acc[i][j] = 0.0f;
    }

    const int r0 = ty * 4;

    for (int kt = 0; kt < T_DIM; kt += 64) {
        __syncthreads();
#pragma unroll
        for (int s = 0; s < 4; s++) {
            int e = (tid + s * 256) * 4;
            int r = e >> 6, d = e & 63;
            *reinterpret_cast<float4*>(&Ks[r * KPITCH + d]) =
                *reinterpret_cast<const float4*>(&Kg[(size_t)(kt + r) * DH + d]);
            *reinterpret_cast<float4*>(&Vs[r * 64 + d]) =
                *reinterpret_cast<const float4*>(&Vg[(size_t)(kt + r) * DH + d]);
        }
        __syncthreads();

        float s4[4][4];
#pragma unroll
        for (int i = 0; i < 4; i++)
#pragma unroll
            for (int j = 0; j < 4; j++) s4[i][j] = 0.0f;

#pragma unroll
        for (int d = 0; d < 64; d += 4) {
            float4 q4[4], k4[4];
#pragma unroll
            for (int i = 0; i < 4; i++)
                q4[i] = *reinterpret_cast<float4*>(&Qs[(r0 + i) * 64 + d]);
#pragma unroll
            for (int j = 0; j < 4; j++)
                k4[j] = *reinterpret_cast<float4*>(&Ks[(tx + j * 16) * KPITCH + d]);
#pragma unroll
            for (int i = 0; i < 4; i++)
#pragma unroll
                for (int j = 0; j < 4; j++) {
                    s4[i][j] += q4[i].x * k4[j].x;
                    s4[i][j] += q4[i].y * k4[j].y;
                    s4[i][j] += q4[i].z * k4[j].z;
                    s4[i][j] += q4[i].w * k4[j].w;
                }
        }

#pragma unroll
        for (int i = 0; i < 4; i++) {
            float mx = fmaxf(fmaxf(s4[i][0], s4[i][1]), fmaxf(s4[i][2], s4[i][3]));
#pragma unroll
            for (int o = 8; o >= 1; o >>= 1)
                mx = fmaxf(mx, __shfl_xor_sync(0xffffffffu, mx, o));
            float m_new = fmaxf(m_i[i], mx);
            float corr = __expf(m_i[i] - m_new);
            float lsum = 0.0f;
#pragma unroll
            for (int j = 0; j < 4; j++) {
                s4[i][j] = __expf(s4[i][j] - m_new);
                lsum += s4[i][j];
            }
#pragma unroll
            for (int o = 8; o >= 1; o >>= 1)
                lsum += __shfl_xor_sync(0xffffffffu, lsum, o);
            l_i[i] = l_i[i] * corr + lsum;
            m_i[i] = m_new;
#pragma unroll
            for (int j = 0; j < 4; j++) acc[i][j] *= corr;
        }

        __syncthreads();
#pragma unroll
        for (int i = 0; i < 4; i++)
#pragma unroll
            for (int j = 0; j < 4; j++)
                Ks[(r0 + i) * KPITCH + tx + j * 16] = s4[i][j];
        __syncthreads();

#pragma unroll
        for (int c = 0; c < 64; c += 4) {
            float pr[4][4];
#pragma unroll
            for (int i = 0; i < 4; i++) {
                float4 p4 = *reinterpret_cast<float4*>(&Ks[(r0 + i) * KPITCH + c]);
                pr[i][0] = p4.x; pr[i][1] = p4.y; pr[i][2] = p4.z; pr[i][3] = p4.w;
            }
#pragma unroll
            for (int cc = 0; cc < 4; cc++) {
                float vv[4];
#pragma unroll
                for (int jj = 0; jj < 4; jj++)
                    vv[jj] = Vs[(c + cc) * 64 + tx + jj * 16];
#pragma unroll
                for (int i = 0; i < 4; i++)
#pragma unroll
                    for (int jj = 0; jj < 4; jj++)
                        acc[i][jj] += pr[i][cc] * vv[jj];
            }
        }
    }

    // Epilogue: normalize, write bf16 hi/lo into g_Ahi/g_Alo [t*B+b][h*DH+d]
    const int b = bh >> 4;
    const int h = bh & 15;
#pragma unroll
    for (int i = 0; i < 4; i++) {
        int t = q0 + r0 + i;
        float inv = 1.0f / l_i[i];
#pragma unroll
        for (int jj = 0; jj < 4; jj++) {
            int d = tx + jj * 16;
            float o = acc[i][jj] * inv;
            __nv_bfloat16 oh = __float2bfloat16(o);
            __nv_bfloat16 ol = __float2bfloat16(o - __bfloat162float(oh));
            size_t idx = ((size_t)t * B_DIM + b) * E_DIM + h * DH + d;
            g_Ahi[idx] = oh;
            g_Alo[idx] = ol;
        }
    }
}

// ---------------------------------------------------------------------------
// Launch
// inputs: 0=query, 1=key(unused), 2=value(unused), 3=in_proj_weight,
//         4=in_proj_bias, 5=out_w, 6=out_b
// ---------------------------------------------------------------------------
extern "C" void kernel_launch(void* const* d_in, const int* in_sizes, int n_in,
                              void* d_out, int out_size)
{
    const float* query = (const float*)d_in[0];
    const float* in_w  = (const float*)d_in[3];
    const float* in_b  = (const float*)d_in[4];
    const float* out_w = (const float*)d_in[5];
    const float* out_b = (const float*)d_in[6];
    float* out = (float*)d_out;

    __nv_bfloat16 *xhi, *xlo, *whi, *wlo, *owhi, *owlo, *ahi, *alo;
    cudaGetSymbolAddress((void**)&xhi,  g_Xhi);  cudaGetSymbolAddress((void**)&xlo,  g_Xlo);
    cudaGetSymbolAddress((void**)&whi,  g_Whi);  cudaGetSymbolAddress((void**)&wlo,  g_Wlo);
    cudaGetSymbolAddress((void**)&owhi, g_OWhi); cudaGetSymbolAddress((void**)&owlo, g_OWlo);
    cudaGetSymbolAddress((void**)&ahi,  g_Ahi);  cudaGetSymbolAddress((void**)&alo,  g_Alo);

    // 0) fp32 -> bf16 hi/lo splits
    cvt_split_kernel<<<(TB * E_DIM / 4 + 255) / 256, 256>>>(query, xhi, xlo, TB * E_DIM / 4);
    cvt_split_kernel<<<(E3 * E_DIM / 4 + 255) / 256, 256>>>(in_w, whi, wlo, E3 * E_DIM / 4);
    cvt_split_kernel<<<(E_DIM * E_DIM / 4 + 255) / 256, 256>>>(out_w, owhi, owlo, E_DIM * E_DIM / 4);

    // 1) QKV projection via HMMA
    hmma_gemm_kernel<0><<<dim3(E3 / 128, TB / 128), 256>>>(xhi, xlo, whi, wlo, in_b, nullptr);

    // 2) Flash attention (scalar fp32)
    const int fa_smem = (64 * 64 + 64 * KPITCH + 64 * 64) * (int)sizeof(float);
    cudaFuncSetAttribute(flash_attn_kernel,
                         cudaFuncAttributeMaxDynamicSharedMemorySize, fa_smem);
    flash_attn_kernel<<<dim3(B_DIM * H_DIM, T_DIM / 64), 256, fa_smem>>>();

    // 3) Output projection via HMMA
    hmma_gemm_kernel<1><<<dim3(E_DIM / 128, TB / 128), 256>>>(ahi, alo, owhi, owlo, out_b, out);
}

// round 6
// speedup vs baseline: 1.6177x; 1.2182x over previous
#include <cuda_runtime.h>
#include <cuda_bf16.h>
#include <cstdint>

// Problem constants
#define T_DIM 2048
#define B_DIM 2
#define E_DIM 1024
#define H_DIM 16
#define DH    64
#define TB    (T_DIM * B_DIM)   // 4096
#define E3    (3 * E_DIM)       // 3072

// ---------------------------------------------------------------------------
// Device scratch (no runtime allocation allowed)
// ---------------------------------------------------------------------------
__device__ float g_Q[B_DIM * H_DIM * T_DIM * DH];   // [B*H][T][DH], pre-scaled
__device__ float g_K[B_DIM * H_DIM * T_DIM * DH];
__device__ float g_V[B_DIM * H_DIM * T_DIM * DH];

__device__ __nv_bfloat16 g_Xhi[TB * E_DIM],  g_Xlo[TB * E_DIM];        // query split
__device__ __nv_bfloat16 g_Whi[E3 * E_DIM],  g_Wlo[E3 * E_DIM];        // in_proj_weight split
__device__ __nv_bfloat16 g_OWhi[E_DIM * E_DIM], g_OWlo[E_DIM * E_DIM]; // out_w split
__device__ __nv_bfloat16 g_Ahi[TB * E_DIM],  g_Alo[TB * E_DIM];        // attn output split

// ---------------------------------------------------------------------------
// Helpers (all proven in the passing R3 kernel, plus scalar bf16 packing)
// ---------------------------------------------------------------------------
__device__ __forceinline__ uint32_t smem_u32(const void* p) {
    uint32_t a;
    asm("{ .reg .u64 t; cvta.to.shared.u64 t, %1; cvt.u32.u64 %0, t; }" : "=r"(a) : "l"(p));
    return a;
}

__device__ __forceinline__ void ldsm_x4(uint32_t& r0, uint32_t& r1, uint32_t& r2,
                                        uint32_t& r3, uint32_t addr) {
    asm volatile("ldmatrix.sync.aligned.m8n8.x4.shared.b16 {%0,%1,%2,%3}, [%4];"
                 : "=r"(r0), "=r"(r1), "=r"(r2), "=r"(r3) : "r"(addr));
}

__device__ __forceinline__ void mma_bf16(float* d, const uint32_t* a, const uint32_t* b) {
    asm volatile(
        "mma.sync.aligned.m16n8k16.row.col.f32.bf16.bf16.f32 "
        "{%0,%1,%2,%3}, {%4,%5,%6,%7}, {%8,%9}, {%0,%1,%2,%3};"
        : "+f"(d[0]), "+f"(d[1]), "+f"(d[2]), "+f"(d[3])
        : "r"(a[0]), "r"(a[1]), "r"(a[2]), "r"(a[3]), "r"(b[0]), "r"(b[1]));
}

// Scalar hi/lo packing (same math as R3's passing cvt kernel)
__device__ __forceinline__ uint32_t pack2(float a, float b) {
    __nv_bfloat162 p(__float2bfloat16(a), __float2bfloat16(b));
    return *reinterpret_cast<uint32_t*>(&p);
}
__device__ __forceinline__ uint32_t pack_hi2(float a, float b, float& ra, float& rb) {
    __nv_bfloat16 ha = __float2bfloat16(a), hb = __float2bfloat16(b);
    ra = a - __bfloat162float(ha);
    rb = b - __bfloat162float(hb);
    __nv_bfloat162 p(ha, hb);
    return *reinterpret_cast<uint32_t*>(&p);
}

// ---------------------------------------------------------------------------
// Kernel 0: fp32 -> (bf16 hi, bf16 lo) split conversion (EXACT R3 version)
// ---------------------------------------------------------------------------
__global__ __launch_bounds__(256) void cvt_split_kernel(
    const float* __restrict__ x, __nv_bfloat16* __restrict__ hi,
    __nv_bfloat16* __restrict__ lo, int n4)
{
    int i = blockIdx.x * blockDim.x + threadIdx.x;
    if (i >= n4) return;
    float4 v = reinterpret_cast<const float4*>(x)[i];
    __nv_bfloat16 h0 = __float2bfloat16(v.x), h1 = __float2bfloat16(v.y);
    __nv_bfloat16 h2 = __float2bfloat16(v.z), h3 = __float2bfloat16(v.w);
    __nv_bfloat16 l0 = __float2bfloat16(v.x - __bfloat162float(h0));
    __nv_bfloat16 l1 = __float2bfloat16(v.y - __bfloat162float(h1));
    __nv_bfloat16 l2 = __float2bfloat16(v.z - __bfloat162float(h2));
    __nv_bfloat16 l3 = __float2bfloat16(v.w - __bfloat162float(h3));
    __nv_bfloat162* hp = reinterpret_cast<__nv_bfloat162*>(hi);
    __nv_bfloat162* lp = reinterpret_cast<__nv_bfloat162*>(lo);
    hp[2 * i + 0] = __nv_bfloat162(h0, h1);
    hp[2 * i + 1] = __nv_bfloat162(h2, h3);
    lp[2 * i + 0] = __nv_bfloat162(l0, l1);
    lp[2 * i + 1] = __nv_bfloat162(l2, l3);
}

// ---------------------------------------------------------------------------
// HMMA split-bf16 GEMM — EXACT R3 (passing) version, no prefetch.
// MODE 0: QKV -> scatter fp32 g_Q (*0.125), g_K, g_V.  MODE 1: out-proj.
// ---------------------------------------------------------------------------
#define BK     32
#define PITCH  80
#define BUFSZ  (128 * PITCH)   // 10240

template<int MODE>
__global__ __launch_bounds__(256) void hmma_gemm_kernel(
    const __nv_bfloat16* __restrict__ Ahi, const __nv_bfloat16* __restrict__ Alo,
    const __nv_bfloat16* __restrict__ Bhi, const __nv_bfloat16* __restrict__ Blo,
    const float* __restrict__ bias, float* __restrict__ out)
{
    __shared__ char smem[4 * BUFSZ];
    char* sAh = smem;
    char* sAl = smem + BUFSZ;
    char* sBh = smem + 2 * BUFSZ;
    char* sBl = smem + 3 * BUFSZ;

    const int tid  = threadIdx.x;
    const int wid  = tid >> 5;
    const int lane = tid & 31;
    const int wm = wid & 3;
    const int wn = wid >> 2;
    const int rowBase = blockIdx.y * 128;
    const int colBase = blockIdx.x * 128;

    const uint32_t sb_Ah = smem_u32(sAh);
    const uint32_t sb_Al = smem_u32(sAl);
    const uint32_t sb_Bh = smem_u32(sBh);
    const uint32_t sb_Bl = smem_u32(sBl);

    float acc[2][8][4];
#pragma unroll
    for (int i = 0; i < 2; i++)
#pragma unroll
        for (int j = 0; j < 8; j++)
#pragma unroll
            for (int k = 0; k < 4; k++) acc[i][j][k] = 0.0f;

    const uint32_t aoff = (uint32_t)((wm * 32 + (lane & 15)) * PITCH + (lane >> 4) * 16);
    const uint32_t boff = (uint32_t)((wn * 64 + (lane >> 4) * 8 + (lane & 7)) * PITCH +
                                     ((lane >> 3) & 1) * 16);

    for (int k0 = 0; k0 < E_DIM; k0 += BK) {
        __syncthreads();
#pragma unroll
        for (int s = 0; s < 2; s++) {
            int unit = tid + s * 256;
            int row = unit >> 2, seg = unit & 3;
            uint32_t so = (uint32_t)(row * PITCH + seg * 16);
            size_t ao = (size_t)(rowBase + row) * E_DIM + k0 + seg * 8;
            size_t bo = (size_t)(colBase + row) * E_DIM + k0 + seg * 8;
            *reinterpret_cast<uint4*>(sAh + so) = *reinterpret_cast<const uint4*>(Ahi + ao);
            *reinterpret_cast<uint4*>(sAl + so) = *reinterpret_cast<const uint4*>(Alo + ao);
            *reinterpret_cast<uint4*>(sBh + so) = *reinterpret_cast<const uint4*>(Bhi + bo);
            *reinterpret_cast<uint4*>(sBl + so) = *reinterpret_cast<const uint4*>(Blo + bo);
        }
        __syncthreads();

#pragma unroll
        for (int ks = 0; ks < BK; ks += 16) {
            const uint32_t kb = (uint32_t)(ks * 2);
            uint32_t ah[2][4], al[2][4];
#pragma unroll
            for (int mt = 0; mt < 2; mt++) {
                uint32_t ar = aoff + (uint32_t)(mt * 16 * PITCH) + kb;
                ldsm_x4(ah[mt][0], ah[mt][1], ah[mt][2], ah[mt][3], sb_Ah + ar);
                ldsm_x4(al[mt][0], al[mt][1], al[mt][2], al[mt][3], sb_Al + ar);
            }
#pragma unroll
            for (int np = 0; np < 4; np++) {
                uint32_t br = boff + (uint32_t)(np * 16 * PITCH) + kb;
                uint32_t bh[4], bl[4];
                ldsm_x4(bh[0], bh[1], bh[2], bh[3], sb_Bh + br);
                ldsm_x4(bl[0], bl[1], bl[2], bl[3], sb_Bl + br);
#pragma unroll
                for (int mt = 0; mt < 2; mt++) {
#pragma unroll
                    for (int j = 0; j < 2; j++) {
                        float* d = acc[mt][np * 2 + j];
                        mma_bf16(d, ah[mt], &bh[j * 2]);
                        mma_bf16(d, ah[mt], &bl[j * 2]);
                        mma_bf16(d, al[mt], &bh[j * 2]);
                    }
                }
            }
        }
    }

    const int rloc = wm * 32 + (lane >> 2);
    const int cloc = wn * 64 + (lane & 3) * 2;

    if (MODE == 0) {
        const int f0 = colBase + wn * 64;
        const int which = f0 >> 10;
        const int h = (f0 & 1023) >> 6;
        float* base;
        float scale;
        if (which == 0)      { base = g_Q; scale = 0.125f; }
        else if (which == 1) { base = g_K; scale = 1.0f; }
        else                 { base = g_V; scale = 1.0f; }
#pragma unroll
        for (int mt = 0; mt < 2; mt++) {
#pragma unroll
            for (int half = 0; half < 2; half++) {
                int r = rowBase + rloc + mt * 16 + half * 8;
                int t = r >> 1, bb = r & 1;
                float* dst = base + ((size_t)(bb * H_DIM + h) * T_DIM + t) * DH;
#pragma unroll
                for (int nt = 0; nt < 8; nt++) {
                    int d = (nt * 8) + (cloc & 63);
                    float2 v;
                    v.x = (acc[mt][nt][half * 2 + 0] + bias[f0 + d])     * scale;
                    v.y = (acc[mt][nt][half * 2 + 1] + bias[f0 + d + 1]) * scale;
                    *reinterpret_cast<float2*>(dst + d) = v;
                }
            }
        }
    } else {
#pragma unroll
        for (int mt = 0; mt < 2; mt++) {
#pragma unroll
            for (int half = 0; half < 2; half++) {
                int r = rowBase + rloc + mt * 16 + half * 8;
                float* dst = out + (size_t)r * E_DIM;
#pragma unroll
                for (int nt = 0; nt < 8; nt++) {
                    int c = colBase + wn * 64 + nt * 8 + (lane & 3) * 2;
                    float2 v;
                    v.x = acc[mt][nt][half * 2 + 0] + bias[c];
                    v.y = acc[mt][nt][half * 2 + 1] + bias[c + 1];
                    *reinterpret_cast<float2*>(dst + c) = v;
                }
            }
        }
    }
}

// ---------------------------------------------------------------------------
// Kernel 2: HMMA flash attention. Reads fp32 g_Q/g_K/g_V, converts to hi/lo
// bf16 during staging. P goes through shared memory (no C->A register reuse).
// V transposed in smem (no trans-ldmatrix). 128 threads = 4 warps; warp w
// owns q rows w*16..w*16+15 of a 64-row tile.
// Buffers [64][72] bf16, pitch 144B: Qh Ql | Kh Kl (reused for P) | Vth Vtl.
// ---------------------------------------------------------------------------
#define FPITCH 72
#define FPB    (FPITCH * 2)          // 144 bytes/row
#define FBUF   (64 * FPB)            // 9216 bytes
#define FSMEM  (6 * FBUF)            // 55296 bytes

__global__ __launch_bounds__(128) void flash_hmma_kernel()
{
    extern __shared__ char fsm[];
    char* sQh = fsm;
    char* sQl = fsm + FBUF;
    char* sKh = fsm + 2 * FBUF;      // reused for P-hi after S stage
    char* sKl = fsm + 3 * FBUF;      // reused for P-lo
    char* sVt = fsm + 4 * FBUF;
    char* sVl = fsm + 5 * FBUF;

    const int tid = threadIdx.x;
    const int lane = tid & 31;
    const int w = tid >> 5;
    const int bh = blockIdx.x;
    const int q0 = blockIdx.y * 64;

    const size_t hbase = (size_t)bh * T_DIM * DH;
    const float* Qg = g_Q + hbase;
    const float* Kg = g_K + hbase;
    const float* Vg = g_V + hbase;

    // Stage Q tile: fp32 -> hi/lo bf16, rows = q
#pragma unroll
    for (int s = 0; s < 8; s++) {
        int unit = tid + s * 128;            // 0..1023
        int row = unit >> 4;                 // 0..63
        int c4 = (unit & 15) * 4;            // 0..60
        float4 q = *reinterpret_cast<const float4*>(Qg + (q0 + row) * DH + c4);
        float r0, r1, r2, r3;
        uint32_t h01 = pack_hi2(q.x, q.y, r0, r1);
        uint32_t h23 = pack_hi2(q.z, q.w, r2, r3);
        uint32_t so = (uint32_t)(row * FPB + c4 * 2);
        *reinterpret_cast<uint2*>(sQh + so) = make_uint2(h01, h23);
        *reinterpret_cast<uint2*>(sQl + so) = make_uint2(pack2(r0, r1), pack2(r2, r3));
    }
    __syncthreads();

    // Persistent Q A-fragments (R3 GEMM A-pattern)
    uint32_t aqh[4][4], aql[4][4];
    const uint32_t qaddr = smem_u32(sQh) +
        (uint32_t)((w * 16 + (lane & 15)) * FPB + (lane >> 4) * 16);
#pragma unroll
    for (int ks = 0; ks < 4; ks++) {
        ldsm_x4(aqh[ks][0], aqh[ks][1], aqh[ks][2], aqh[ks][3], qaddr + ks * 32);
        ldsm_x4(aql[ks][0], aql[ks][1], aql[ks][2], aql[ks][3], qaddr + FBUF + ks * 32);
    }

    float o[8][4];
#pragma unroll
    for (int i = 0; i < 8; i++)
#pragma unroll
        for (int j = 0; j < 4; j++) o[i][j] = 0.0f;
    float m1 = -1e30f, m2 = -1e30f, l1 = 0.0f, l2 = 0.0f;

    // B-operand lane addressing (R3 GEMM B-pattern) for K and Vt
    const uint32_t blanes = (uint32_t)(((lane >> 4) * 8 + (lane & 7)) * FPB +
                                       ((lane >> 3) & 1) * 16);
    const uint32_t kaddr = smem_u32(sKh) + blanes;
    const uint32_t vaddr = smem_u32(sVt) + blanes;
    // P A-fragment addressing (same form as Q)
    const uint32_t paddr = smem_u32(sKh) +
        (uint32_t)((w * 16 + (lane & 15)) * FPB + (lane >> 4) * 16);

    const int r1loc = w * 16 + (lane >> 2);
    const int r2loc = r1loc + 8;

    for (int kt = 0; kt < T_DIM; kt += 64) {
        __syncthreads();   // previous iteration's P/V reads complete
        // Stage K (rows=key, cols=d) and V transposed (rows=d, cols=key)
#pragma unroll
        for (int s = 0; s < 8; s++) {
            int unit = tid + s * 128;
            int row = unit >> 4;             // key row 0..63
            int c4 = (unit & 15) * 4;        // d 0..60
            float4 kf = *reinterpret_cast<const float4*>(Kg + (kt + row) * DH + c4);
            float r0, r1, r2, r3;
            uint32_t h01 = pack_hi2(kf.x, kf.y, r0, r1);
            uint32_t h23 = pack_hi2(kf.z, kf.w, r2, r3);
            uint32_t so = (uint32_t)(row * FPB + c4 * 2);
            *reinterpret_cast<uint2*>(sKh + so) = make_uint2(h01, h23);
            *reinterpret_cast<uint2*>(sKl + so) = make_uint2(pack2(r0, r1), pack2(r2, r3));

            float4 vf = *reinterpret_cast<const float4*>(Vg + (kt + row) * DH + c4);
            float ve[4] = {vf.x, vf.y, vf.z, vf.w};
#pragma unroll
            for (int e = 0; e < 4; e++) {
                __nv_bfloat16 vh = __float2bfloat16(ve[e]);
                __nv_bfloat16 vl = __float2bfloat16(ve[e] - __bfloat162float(vh));
                uint32_t vo = (uint32_t)((c4 + e) * FPB + row * 2);
                *reinterpret_cast<__nv_bfloat16*>(sVt + vo) = vh;
                *reinterpret_cast<__nv_bfloat16*>(sVl + vo) = vl;
            }
        }
        __syncthreads();

        // S = Q K^T (warp: 16 q-rows x 64 keys)
        float s4[8][4];
#pragma unroll
        for (int i = 0; i < 8; i++)
#pragma unroll
            for (int j = 0; j < 4; j++) s4[i][j] = 0.0f;

#pragma unroll
        for (int ks = 0; ks < 4; ks++) {
#pragma unroll
            for (int np = 0; np < 4; np++) {
                uint32_t ba = kaddr + (uint32_t)(np * 16 * FPB) + ks * 32;
                uint32_t bh[4], bl[4];
                ldsm_x4(bh[0], bh[1], bh[2], bh[3], ba);
                ldsm_x4(bl[0], bl[1], bl[2], bl[3], ba + FBUF);
#pragma unroll
                for (int j = 0; j < 2; j++) {
                    float* d = s4[np * 2 + j];
                    mma_bf16(d, aqh[ks], &bh[j * 2]);
                    mma_bf16(d, aqh[ks], &bl[j * 2]);
                    mma_bf16(d, aql[ks], &bh[j * 2]);
                }
            }
        }

        // Online softmax (C layout: rows r1loc / r2loc, cols nt*8 + 2*(lane&3))
        float mx1 = -1e30f, mx2 = -1e30f;
#pragma unroll
        for (int nt = 0; nt < 8; nt++) {
            mx1 = fmaxf(mx1, fmaxf(s4[nt][0], s4[nt][1]));
            mx2 = fmaxf(mx2, fmaxf(s4[nt][2], s4[nt][3]));
        }
        mx1 = fmaxf(mx1, __shfl_xor_sync(0xffffffffu, mx1, 1));
        mx1 = fmaxf(mx1, __shfl_xor_sync(0xffffffffu, mx1, 2));
        mx2 = fmaxf(mx2, __shfl_xor_sync(0xffffffffu, mx2, 1));
        mx2 = fmaxf(mx2, __shfl_xor_sync(0xffffffffu, mx2, 2));

        float mn1 = fmaxf(m1, mx1), mn2 = fmaxf(m2, mx2);
        float c1 = __expf(m1 - mn1), c2 = __expf(m2 - mn2);
        m1 = mn1; m2 = mn2;

        float p1 = 0.0f, p2 = 0.0f;
#pragma unroll
        for (int nt = 0; nt < 8; nt++) {
            s4[nt][0] = __expf(s4[nt][0] - mn1); p1 += s4[nt][0];
            s4[nt][1] = __expf(s4[nt][1] - mn1); p1 += s4[nt][1];
            s4[nt][2] = __expf(s4[nt][2] - mn2); p2 += s4[nt][2];
            s4[nt][3] = __expf(s4[nt][3] - mn2); p2 += s4[nt][3];
        }
        l1 = l1 * c1 + p1;
        l2 = l2 * c2 + p2;
#pragma unroll
        for (int nt = 0; nt < 8; nt++) {
            o[nt][0] *= c1; o[nt][1] *= c1;
            o[nt][2] *= c2; o[nt][3] *= c2;
        }

        __syncthreads();   // all warps finished reading K before P overwrites it
        // Store P (hi/lo) into the K buffers: row = q-row, col = key
#pragma unroll
        for (int nt = 0; nt < 8; nt++) {
            int col = nt * 8 + (lane & 3) * 2;
            float ra, rb;
            uint32_t ph = pack_hi2(s4[nt][0], s4[nt][1], ra, rb);
            uint32_t so1 = (uint32_t)(r1loc * FPB + col * 2);
            *reinterpret_cast<uint32_t*>(sKh + so1) = ph;
            *reinterpret_cast<uint32_t*>(sKl + so1) = pack2(ra, rb);
            ph = pack_hi2(s4[nt][2], s4[nt][3], ra, rb);
            uint32_t so2 = (uint32_t)(r2loc * FPB + col * 2);
            *reinterpret_cast<uint32_t*>(sKh + so2) = ph;
            *reinterpret_cast<uint32_t*>(sKl + so2) = pack2(ra, rb);
        }
        __syncwarp();      // warp reads only its own 16 P rows

        // O += P V  (A-frags from smem P; B-frags from smem Vt)
#pragma unroll
        for (int ks = 0; ks < 4; ks++) {
            uint32_t pah[4], pal[4];
            ldsm_x4(pah[0], pah[1], pah[2], pah[3], paddr + ks * 32);
            ldsm_x4(pal[0], pal[1], pal[2], pal[3], paddr + FBUF + ks * 32);
#pragma unroll
            for (int np = 0; np < 4; np++) {
                uint32_t ba = vaddr + (uint32_t)(np * 16 * FPB) + ks * 32;
                uint32_t bvh[4], bvl[4];
                ldsm_x4(bvh[0], bvh[1], bvh[2], bvh[3], ba);
                ldsm_x4(bvl[0], bvl[1], bvl[2], bvl[3], ba + FBUF);
#pragma unroll
                for (int j = 0; j < 2; j++) {
                    float* d = o[np * 2 + j];
                    mma_bf16(d, pah, &bvh[j * 2]);
                    mma_bf16(d, pah, &bvl[j * 2]);
                    mma_bf16(d, pal, &bvh[j * 2]);
                }
            }
        }
    }

    // Epilogue: normalize, write bf16 hi/lo to g_Ahi/g_Alo [t*B+b][h*DH+d]
    l1 += __shfl_xor_sync(0xffffffffu, l1, 1);
    l1 += __shfl_xor_sync(0xffffffffu, l1, 2);
    l2 += __shfl_xor_sync(0xffffffffu, l2, 1);
    l2 += __shfl_xor_sync(0xffffffffu, l2, 2);
    const float inv1 = 1.0f / l1, inv2 = 1.0f / l2;

    const int r1 = q0 + r1loc;
    const int r2 = q0 + r2loc;
    const int b = bh >> 4;
    const int h = bh & 15;

#pragma unroll
    for (int nt = 0; nt < 8; nt++) {
        int d = nt * 8 + (lane & 3) * 2;
        float ra, rb;
        uint32_t hh = pack_hi2(o[nt][0] * inv1, o[nt][1] * inv1, ra, rb);
        size_t i1 = ((size_t)r1 * B_DIM + b) * E_DIM + h * DH + d;
        *reinterpret_cast<uint32_t*>(&g_Ahi[i1]) = hh;
        *reinterpret_cast<uint32_t*>(&g_Alo[i1]) = pack2(ra, rb);
        hh = pack_hi2(o[nt][2] * inv2, o[nt][3] * inv2, ra, rb);
        size_t i2 = ((size_t)r2 * B_DIM + b) * E_DIM + h * DH + d;
        *reinterpret_cast<uint32_t*>(&g_Ahi[i2]) = hh;
        *reinterpret_cast<uint32_t*>(&g_Alo[i2]) = pack2(ra, rb);
    }
}

// ---------------------------------------------------------------------------
// Launch
// inputs: 0=query, 1=key(unused), 2=value(unused), 3=in_proj_weight,
//         4=in_proj_bias, 5=out_w, 6=out_b
// ---------------------------------------------------------------------------
extern "C" void kernel_launch(void* const* d_in, const int* in_sizes, int n_in,
                              void* d_out, int out_size)
{
    const float* query = (const float*)d_in[0];
    const float* in_w  = (const float*)d_in[3];
    const float* in_b  = (const float*)d_in[4];
    const float* out_w = (const float*)d_in[5];
    const float* out_b = (const float*)d_in[6];
    float* out = (float*)d_out;

    __nv_bfloat16 *xhi, *xlo, *whi, *wlo, *owhi, *owlo, *ahi, *alo;
    cudaGetSymbolAddress((void**)&xhi,  g_Xhi);  cudaGetSymbolAddress((void**)&xlo,  g_Xlo);
    cudaGetSymbolAddress((void**)&whi,  g_Whi);  cudaGetSymbolAddress((void**)&wlo,  g_Wlo);
    cudaGetSymbolAddress((void**)&owhi, g_OWhi); cudaGetSymbolAddress((void**)&owlo, g_OWlo);
    cudaGetSymbolAddress((void**)&ahi,  g_Ahi);  cudaGetSymbolAddress((void**)&alo,  g_Alo);

    // 0) fp32 -> bf16 hi/lo splits
    cvt_split_kernel<<<(TB * E_DIM / 4 + 255) / 256, 256>>>(query, xhi, xlo, TB * E_DIM / 4);
    cvt_split_kernel<<<(E3 * E_DIM / 4 + 255) / 256, 256>>>(in_w, whi, wlo, E3 * E_DIM / 4);
    cvt_split_kernel<<<(E_DIM * E_DIM / 4 + 255) / 256, 256>>>(out_w, owhi, owlo, E_DIM * E_DIM / 4);

    // 1) QKV projection via HMMA (exact R3 passing kernel; fp32 Q/K/V out)
    hmma_gemm_kernel<0><<<dim3(E3 / 128, TB / 128), 256>>>(xhi, xlo, whi, wlo, in_b, nullptr);

    // 2) HMMA flash attention (GEMM-proven ldmatrix patterns only)
    cudaFuncSetAttribute(flash_hmma_kernel,
                         cudaFuncAttributeMaxDynamicSharedMemorySize, FSMEM);
    flash_hmma_kernel<<<dim3(B_DIM * H_DIM, T_DIM / 64), 128, FSMEM>>>();

    // 3) Output projection via HMMA (exact R3 passing kernel)
    hmma_gemm_kernel<1><<<dim3(E_DIM / 128, TB / 128), 256>>>(ahi, alo, owhi, owlo, out_b, out);
}

// round 9
// speedup vs baseline: 2.0732x; 1.2816x over previous
#include <cuda_runtime.h>
#include <cuda_bf16.h>
#include <cstdint>

// Problem constants
#define T_DIM 2048
#define B_DIM 2
#define E_DIM 1024
#define H_DIM 16
#define DH    64
#define TB    (T_DIM * B_DIM)   // 4096
#define E3    (3 * E_DIM)       // 3072

// ---------------------------------------------------------------------------
// Device scratch (no runtime allocation allowed)
// ---------------------------------------------------------------------------
__device__ float g_Q[B_DIM * H_DIM * T_DIM * DH];   // [B*H][T][DH], pre-scaled
__device__ float g_K[B_DIM * H_DIM * T_DIM * DH];
__device__ float g_V[B_DIM * H_DIM * T_DIM * DH];

__device__ __nv_bfloat16 g_Xhi[TB * E_DIM],  g_Xlo[TB * E_DIM];        // query split
__device__ __nv_bfloat16 g_Whi[E3 * E_DIM],  g_Wlo[E3 * E_DIM];        // in_proj_weight split
__device__ __nv_bfloat16 g_OWhi[E_DIM * E_DIM], g_OWlo[E_DIM * E_DIM]; // out_w split
__device__ __nv_bfloat16 g_Ahi[TB * E_DIM],  g_Alo[TB * E_DIM];        // attn output split

// ---------------------------------------------------------------------------
// Helpers (R3/R6-proven)
// ---------------------------------------------------------------------------
__device__ __forceinline__ uint32_t smem_u32(const void* p) {
    uint32_t a;
    asm("{ .reg .u64 t; cvta.to.shared.u64 t, %1; cvt.u32.u64 %0, t; }" : "=r"(a) : "l"(p));
    return a;
}

__device__ __forceinline__ void ldsm_x4(uint32_t& r0, uint32_t& r1, uint32_t& r2,
                                        uint32_t& r3, uint32_t addr) {
    asm volatile("ldmatrix.sync.aligned.m8n8.x4.shared.b16 {%0,%1,%2,%3}, [%4];"
                 : "=r"(r0), "=r"(r1), "=r"(r2), "=r"(r3) : "r"(addr));
}

__device__ __forceinline__ void mma_bf16(float* d, const uint32_t* a, const uint32_t* b) {
    asm volatile(
        "mma.sync.aligned.m16n8k16.row.col.f32.bf16.bf16.f32 "
        "{%0,%1,%2,%3}, {%4,%5,%6,%7}, {%8,%9}, {%0,%1,%2,%3};"
        : "+f"(d[0]), "+f"(d[1]), "+f"(d[2]), "+f"(d[3])
        : "r"(a[0]), "r"(a[1]), "r"(a[2]), "r"(a[3]), "r"(b[0]), "r"(b[1]));
}

// Scalar hi/lo packing (proven in R3/R6)
__device__ __forceinline__ uint32_t pack2(float a, float b) {
    __nv_bfloat162 p(__float2bfloat16(a), __float2bfloat16(b));
    return *reinterpret_cast<uint32_t*>(&p);
}
__device__ __forceinline__ uint32_t pack_hi2(float a, float b, float& ra, float& rb) {
    __nv_bfloat16 ha = __float2bfloat16(a), hb = __float2bfloat16(b);
    ra = a - __bfloat162float(ha);
    rb = b - __bfloat162float(hb);
    __nv_bfloat162 p(ha, hb);
    return *reinterpret_cast<uint32_t*>(&p);
}

// ---------------------------------------------------------------------------
// Kernel 0: fp32 -> (bf16 hi, bf16 lo) split conversion (EXACT R3/R6 version)
// ---------------------------------------------------------------------------
__global__ __launch_bounds__(256) void cvt_split_kernel(
    const float* __restrict__ x, __nv_bfloat16* __restrict__ hi,
    __nv_bfloat16* __restrict__ lo, int n4)
{
    int i = blockIdx.x * blockDim.x + threadIdx.x;
    if (i >= n4) return;
    float4 v = reinterpret_cast<const float4*>(x)[i];
    __nv_bfloat16 h0 = __float2bfloat16(v.x), h1 = __float2bfloat16(v.y);
    __nv_bfloat16 h2 = __float2bfloat16(v.z), h3 = __float2bfloat16(v.w);
    __nv_bfloat16 l0 = __float2bfloat16(v.x - __bfloat162float(h0));
    __nv_bfloat16 l1 = __float2bfloat16(v.y - __bfloat162float(h1));
    __nv_bfloat16 l2 = __float2bfloat16(v.z - __bfloat162float(h2));
    __nv_bfloat16 l3 = __float2bfloat16(v.w - __bfloat162float(h3));
    __nv_bfloat162* hp = reinterpret_cast<__nv_bfloat162*>(hi);
    __nv_bfloat162* lp = reinterpret_cast<__nv_bfloat162*>(lo);
    hp[2 * i + 0] = __nv_bfloat162(h0, h1);
    hp[2 * i + 1] = __nv_bfloat162(h2, h3);
    lp[2 * i + 0] = __nv_bfloat162(l0, l1);
    lp[2 * i + 1] = __nv_bfloat162(l2, l3);
}

// ---------------------------------------------------------------------------
// HMMA split-bf16 GEMM — EXACT R6 (passing) version. NO pipelining.
// MODE 0: QKV -> scatter fp32 g_Q (*0.125), g_K, g_V.  MODE 1: out-proj.
// ---------------------------------------------------------------------------
#define BK     32
#define PITCH  80
#define BUFSZ  (128 * PITCH)   // 10240

template<int MODE>
__global__ __launch_bounds__(256) void hmma_gemm_kernel(
    const __nv_bfloat16* __restrict__ Ahi, const __nv_bfloat16* __restrict__ Alo,
    const __nv_bfloat16* __restrict__ Bhi, const __nv_bfloat16* __restrict__ Blo,
    const float* __restrict__ bias, float* __restrict__ out)
{
    __shared__ char smem[4 * BUFSZ];
    char* sAh = smem;
    char* sAl = smem + BUFSZ;
    char* sBh = smem + 2 * BUFSZ;
    char* sBl = smem + 3 * BUFSZ;

    const int tid  = threadIdx.x;
    const int wid  = tid >> 5;
    const int lane = tid & 31;
    const int wm = wid & 3;
    const int wn = wid >> 2;
    const int rowBase = blockIdx.y * 128;
    const int colBase = blockIdx.x * 128;

    const uint32_t sb_Ah = smem_u32(sAh);
    const uint32_t sb_Al = smem_u32(sAl);
    const uint32_t sb_Bh = smem_u32(sBh);
    const uint32_t sb_Bl = smem_u32(sBl);

    float acc[2][8][4];
#pragma unroll
    for (int i = 0; i < 2; i++)
#pragma unroll
        for (int j = 0; j < 8; j++)
#pragma unroll
            for (int k = 0; k < 4; k++) acc[i][j][k] = 0.0f;

    const uint32_t aoff = (uint32_t)((wm * 32 + (lane & 15)) * PITCH + (lane >> 4) * 16);
    const uint32_t boff = (uint32_t)((wn * 64 + (lane >> 4) * 8 + (lane & 7)) * PITCH +
                                     ((lane >> 3) & 1) * 16);

    for (int k0 = 0; k0 < E_DIM; k0 += BK) {
        __syncthreads();
#pragma unroll
        for (int s = 0; s < 2; s++) {
            int unit = tid + s * 256;
            int row = unit >> 2, seg = unit & 3;
            uint32_t so = (uint32_t)(row * PITCH + seg * 16);
            size_t ao = (size_t)(rowBase + row) * E_DIM + k0 + seg * 8;
            size_t bo = (size_t)(colBase + row) * E_DIM + k0 + seg * 8;
            *reinterpret_cast<uint4*>(sAh + so) = *reinterpret_cast<const uint4*>(Ahi + ao);
            *reinterpret_cast<uint4*>(sAl + so) = *reinterpret_cast<const uint4*>(Alo + ao);
            *reinterpret_cast<uint4*>(sBh + so) = *reinterpret_cast<const uint4*>(Bhi + bo);
            *reinterpret_cast<uint4*>(sBl + so) = *reinterpret_cast<const uint4*>(Blo + bo);
        }
        __syncthreads();

#pragma unroll
        for (int ks = 0; ks < BK; ks += 16) {
            const uint32_t kb = (uint32_t)(ks * 2);
            uint32_t ah[2][4], al[2][4];
#pragma unroll
            for (int mt = 0; mt < 2; mt++) {
                uint32_t ar = aoff + (uint32_t)(mt * 16 * PITCH) + kb;
                ldsm_x4(ah[mt][0], ah[mt][1], ah[mt][2], ah[mt][3], sb_Ah + ar);
                ldsm_x4(al[mt][0], al[mt][1], al[mt][2], al[mt][3], sb_Al + ar);
            }
#pragma unroll
            for (int np = 0; np < 4; np++) {
                uint32_t br = boff + (uint32_t)(np * 16 * PITCH) + kb;
                uint32_t bh[4], bl[4];
                ldsm_x4(bh[0], bh[1], bh[2], bh[3], sb_Bh + br);
                ldsm_x4(bl[0], bl[1], bl[2], bl[3], sb_Bl + br);
#pragma unroll
                for (int mt = 0; mt < 2; mt++) {
#pragma unroll
                    for (int j = 0; j < 2; j++) {
                        float* d = acc[mt][np * 2 + j];
                        mma_bf16(d, ah[mt], &bh[j * 2]);
                        mma_bf16(d, ah[mt], &bl[j * 2]);
                        mma_bf16(d, al[mt], &bh[j * 2]);
                    }
                }
            }
        }
    }

    const int rloc = wm * 32 + (lane >> 2);
    const int cloc = wn * 64 + (lane & 3) * 2;

    if (MODE == 0) {
        const int f0 = colBase + wn * 64;
        const int which = f0 >> 10;
        const int h = (f0 & 1023) >> 6;
        float* base;
        float scale;
        if (which == 0)      { base = g_Q; scale = 0.125f; }
        else if (which == 1) { base = g_K; scale = 1.0f; }
        else                 { base = g_V; scale = 1.0f; }
#pragma unroll
        for (int mt = 0; mt < 2; mt++) {
#pragma unroll
            for (int half = 0; half < 2; half++) {
                int r = rowBase + rloc + mt * 16 + half * 8;
                int t = r >> 1, bb = r & 1;
                float* dst = base + ((size_t)(bb * H_DIM + h) * T_DIM + t) * DH;
#pragma unroll
                for (int nt = 0; nt < 8; nt++) {
                    int d = (nt * 8) + (cloc & 63);
                    float2 v;
                    v.x = (acc[mt][nt][half * 2 + 0] + bias[f0 + d])     * scale;
                    v.y = (acc[mt][nt][half * 2 + 1] + bias[f0 + d + 1]) * scale;
                    *reinterpret_cast<float2*>(dst + d) = v;
                }
            }
        }
    } else {
#pragma unroll
        for (int mt = 0; mt < 2; mt++) {
#pragma unroll
            for (int half = 0; half < 2; half++) {
                int r = rowBase + rloc + mt * 16 + half * 8;
                float* dst = out + (size_t)r * E_DIM;
#pragma unroll
                for (int nt = 0; nt < 8; nt++) {
                    int c = colBase + wn * 64 + nt * 8 + (lane & 3) * 2;
                    float2 v;
                    v.x = acc[mt][nt][half * 2 + 0] + bias[c];
                    v.y = acc[mt][nt][half * 2 + 1] + bias[c + 1];
                    *reinterpret_cast<float2*>(dst + c) = v;
                }
            }
        }
    }
}

// ---------------------------------------------------------------------------
// Kernel 2: HMMA flash attention — EXACT R6 (passing) kernel with ONE change:
// the V-transpose staging loop uses the (d, 4-key chunk) mapping (coalesced
// global loads, 8B smem stores at 144B stride; smem layout byte-identical).
// ---------------------------------------------------------------------------
#define FPITCH 72
#define FPB    (FPITCH * 2)          // 144 bytes/row
#define FBUF   (64 * FPB)            // 9216 bytes
#define FSMEM  (6 * FBUF)            // 55296 bytes

__global__ __launch_bounds__(128) void flash_hmma_kernel()
{
    extern __shared__ char fsm[];
    char* sQh = fsm;
    char* sQl = fsm + FBUF;
    char* sKh = fsm + 2 * FBUF;      // reused for P-hi after S stage
    char* sKl = fsm + 3 * FBUF;      // reused for P-lo
    char* sVt = fsm + 4 * FBUF;
    char* sVl = fsm + 5 * FBUF;

    const int tid = threadIdx.x;
    const int lane = tid & 31;
    const int w = tid >> 5;
    const int bh = blockIdx.x;
    const int q0 = blockIdx.y * 64;

    const size_t hbase = (size_t)bh * T_DIM * DH;
    const float* Qg = g_Q + hbase;
    const float* Kg = g_K + hbase;
    const float* Vg = g_V + hbase;

    // Stage Q tile: fp32 -> hi/lo bf16, rows = q
#pragma unroll
    for (int s = 0; s < 8; s++) {
        int unit = tid + s * 128;            // 0..1023
        int row = unit >> 4;                 // 0..63
        int c4 = (unit & 15) * 4;            // 0..60
        float4 q = *reinterpret_cast<const float4*>(Qg + (q0 + row) * DH + c4);
        float r0, r1, r2, r3;
        uint32_t h01 = pack_hi2(q.x, q.y, r0, r1);
        uint32_t h23 = pack_hi2(q.z, q.w, r2, r3);
        uint32_t so = (uint32_t)(row * FPB + c4 * 2);
        *reinterpret_cast<uint2*>(sQh + so) = make_uint2(h01, h23);
        *reinterpret_cast<uint2*>(sQl + so) = make_uint2(pack2(r0, r1), pack2(r2, r3));
    }
    __syncthreads();

    // Persistent Q A-fragments
    uint32_t aqh[4][4], aql[4][4];
    const uint32_t qaddr = smem_u32(sQh) +
        (uint32_t)((w * 16 + (lane & 15)) * FPB + (lane >> 4) * 16);
#pragma unroll
    for (int ks = 0; ks < 4; ks++) {
        ldsm_x4(aqh[ks][0], aqh[ks][1], aqh[ks][2], aqh[ks][3], qaddr + ks * 32);
        ldsm_x4(aql[ks][0], aql[ks][1], aql[ks][2], aql[ks][3], qaddr + FBUF + ks * 32);
    }

    float o[8][4];
#pragma unroll
    for (int i = 0; i < 8; i++)
#pragma unroll
        for (int j = 0; j < 4; j++) o[i][j] = 0.0f;
    float m1 = -1e30f, m2 = -1e30f, l1 = 0.0f, l2 = 0.0f;

    const uint32_t blanes = (uint32_t)(((lane >> 4) * 8 + (lane & 7)) * FPB +
                                       ((lane >> 3) & 1) * 16);
    const uint32_t kaddr = smem_u32(sKh) + blanes;
    const uint32_t vaddr = smem_u32(sVt) + blanes;
    const uint32_t paddr = smem_u32(sKh) +
        (uint32_t)((w * 16 + (lane & 15)) * FPB + (lane >> 4) * 16);

    const int r1loc = w * 16 + (lane >> 2);
    const int r2loc = r1loc + 8;

    for (int kt = 0; kt < T_DIM; kt += 64) {
        __syncthreads();   // previous iteration's P/V reads complete
        // Stage K (rows=key, cols=d) — exact R6 loop
#pragma unroll
        for (int s = 0; s < 8; s++) {
            int unit = tid + s * 128;
            int row = unit >> 4;             // key row 0..63
            int c4 = (unit & 15) * 4;        // d 0..60
            float4 kf = *reinterpret_cast<const float4*>(Kg + (kt + row) * DH + c4);
            float r0, r1, r2, r3;
            uint32_t h01 = pack_hi2(kf.x, kf.y, r0, r1);
            uint32_t h23 = pack_hi2(kf.z, kf.w, r2, r3);
            uint32_t so = (uint32_t)(row * FPB + c4 * 2);
            *reinterpret_cast<uint2*>(sKh + so) = make_uint2(h01, h23);
            *reinterpret_cast<uint2*>(sKl + so) = make_uint2(pack2(r0, r1), pack2(r2, r3));
        }
        // Stage V transposed (rows=d, cols=key): NEW mapping (only change vs R6)
#pragma unroll
        for (int s = 0; s < 8; s++) {
            int unit = tid + s * 128;        // 0..1023
            int d = unit & 63;               // Vt row
            int kc = (unit >> 6) * 4;        // key base 0..60
            float v0 = Vg[(kt + kc + 0) * DH + d];
            float v1 = Vg[(kt + kc + 1) * DH + d];
            float v2 = Vg[(kt + kc + 2) * DH + d];
            float v3 = Vg[(kt + kc + 3) * DH + d];
            float r0, r1, r2, r3;
            uint32_t h01 = pack_hi2(v0, v1, r0, r1);
            uint32_t h23 = pack_hi2(v2, v3, r2, r3);
            uint32_t vo = (uint32_t)(d * FPB + kc * 2);
            *reinterpret_cast<uint2*>(sVt + vo) = make_uint2(h01, h23);
            *reinterpret_cast<uint2*>(sVl + vo) = make_uint2(pack2(r0, r1), pack2(r2, r3));
        }
        __syncthreads();

        // S = Q K^T (warp: 16 q-rows x 64 keys)
        float s4[8][4];
#pragma unroll
        for (int i = 0; i < 8; i++)
#pragma unroll
            for (int j = 0; j < 4; j++) s4[i][j] = 0.0f;

#pragma unroll
        for (int ks = 0; ks < 4; ks++) {
#pragma unroll
            for (int np = 0; np < 4; np++) {
                uint32_t ba = kaddr + (uint32_t)(np * 16 * FPB) + ks * 32;
                uint32_t bh[4], bl[4];
                ldsm_x4(bh[0], bh[1], bh[2], bh[3], ba);
                ldsm_x4(bl[0], bl[1], bl[2], bl[3], ba + FBUF);
#pragma unroll
                for (int j = 0; j < 2; j++) {
                    float* d = s4[np * 2 + j];
                    mma_bf16(d, aqh[ks], &bh[j * 2]);
                    mma_bf16(d, aqh[ks], &bl[j * 2]);
                    mma_bf16(d, aql[ks], &bh[j * 2]);
                }
            }
        }

        // Online softmax
        float mx1 = -1e30f, mx2 = -1e30f;
#pragma unroll
        for (int nt = 0; nt < 8; nt++) {
            mx1 = fmaxf(mx1, fmaxf(s4[nt][0], s4[nt][1]));
            mx2 = fmaxf(mx2, fmaxf(s4[nt][2], s4[nt][3]));
        }
        mx1 = fmaxf(mx1, __shfl_xor_sync(0xffffffffu, mx1, 1));
        mx1 = fmaxf(mx1, __shfl_xor_sync(0xffffffffu, mx1, 2));
        mx2 = fmaxf(mx2, __shfl_xor_sync(0xffffffffu, mx2, 1));
        mx2 = fmaxf(mx2, __shfl_xor_sync(0xffffffffu, mx2, 2));

        float mn1 = fmaxf(m1, mx1), mn2 = fmaxf(m2, mx2);
        float c1 = __expf(m1 - mn1), c2 = __expf(m2 - mn2);
        m1 = mn1; m2 = mn2;

        float p1 = 0.0f, p2 = 0.0f;
#pragma unroll
        for (int nt = 0; nt < 8; nt++) {
            s4[nt][0] = __expf(s4[nt][0] - mn1); p1 += s4[nt][0];
            s4[nt][1] = __expf(s4[nt][1] - mn1); p1 += s4[nt][1];
            s4[nt][2] = __expf(s4[nt][2] - mn2); p2 += s4[nt][2];
            s4[nt][3] = __expf(s4[nt][3] - mn2); p2 += s4[nt][3];
        }
        l1 = l1 * c1 + p1;
        l2 = l2 * c2 + p2;
#pragma unroll
        for (int nt = 0; nt < 8; nt++) {
            o[nt][0] *= c1; o[nt][1] *= c1;
            o[nt][2] *= c2; o[nt][3] *= c2;
        }

        __syncthreads();   // all warps finished reading K before P overwrites it
#pragma unroll
        for (int nt = 0; nt < 8; nt++) {
            int col = nt * 8 + (lane & 3) * 2;
            float ra, rb;
            uint32_t ph = pack_hi2(s4[nt][0], s4[nt][1], ra, rb);
            uint32_t so1 = (uint32_t)(r1loc * FPB + col * 2);
            *reinterpret_cast<uint32_t*>(sKh + so1) = ph;
            *reinterpret_cast<uint32_t*>(sKl + so1) = pack2(ra, rb);
            ph = pack_hi2(s4[nt][2], s4[nt][3], ra, rb);
            uint32_t so2 = (uint32_t)(r2loc * FPB + col * 2);
            *reinterpret_cast<uint32_t*>(sKh + so2) = ph;
            *reinterpret_cast<uint32_t*>(sKl + so2) = pack2(ra, rb);
        }
        __syncwarp();      // warp reads only its own 16 P rows

        // O += P V
#pragma unroll
        for (int ks = 0; ks < 4; ks++) {
            uint32_t pah[4], pal[4];
            ldsm_x4(pah[0], pah[1], pah[2], pah[3], paddr + ks * 32);
            ldsm_x4(pal[0], pal[1], pal[2], pal[3], paddr + FBUF + ks * 32);
#pragma unroll
            for (int np = 0; np < 4; np++) {
                uint32_t ba = vaddr + (uint32_t)(np * 16 * FPB) + ks * 32;
                uint32_t bvh[4], bvl[4];
                ldsm_x4(bvh[0], bvh[1], bvh[2], bvh[3], ba);
                ldsm_x4(bvl[0], bvl[1], bvl[2], bvl[3], ba + FBUF);
#pragma unroll
                for (int j = 0; j < 2; j++) {
                    float* d = o[np * 2 + j];
                    mma_bf16(d, pah, &bvh[j * 2]);
                    mma_bf16(d, pah, &bvl[j * 2]);
                    mma_bf16(d, pal, &bvh[j * 2]);
                }
            }
        }
    }

    // Epilogue: normalize, write bf16 hi/lo to g_Ahi/g_Alo [t*B+b][h*DH+d]
    l1 += __shfl_xor_sync(0xffffffffu, l1, 1);
    l1 += __shfl_xor_sync(0xffffffffu, l1, 2);
    l2 += __shfl_xor_sync(0xffffffffu, l2, 1);
    l2 += __shfl_xor_sync(0xffffffffu, l2, 2);
    const float inv1 = 1.0f / l1, inv2 = 1.0f / l2;

    const int r1 = q0 + r1loc;
    const int r2 = q0 + r2loc;
    const int b = bh >> 4;
    const int h = bh & 15;

#pragma unroll
    for (int nt = 0; nt < 8; nt++) {
        int d = nt * 8 + (lane & 3) * 2;
        float ra, rb;
        uint32_t hh = pack_hi2(o[nt][0] * inv1, o[nt][1] * inv1, ra, rb);
        size_t i1 = ((size_t)r1 * B_DIM + b) * E_DIM + h * DH + d;
        *reinterpret_cast<uint32_t*>(&g_Ahi[i1]) = hh;
        *reinterpret_cast<uint32_t*>(&g_Alo[i1]) = pack2(ra, rb);
        hh = pack_hi2(o[nt][2] * inv2, o[nt][3] * inv2, ra, rb);
        size_t i2 = ((size_t)r2 * B_DIM + b) * E_DIM + h * DH + d;
        *reinterpret_cast<uint32_t*>(&g_Ahi[i2]) = hh;
        *reinterpret_cast<uint32_t*>(&g_Alo[i2]) = pack2(ra, rb);
    }
}

// ---------------------------------------------------------------------------
// Launch
// ---------------------------------------------------------------------------
extern "C" void kernel_launch(void* const* d_in, const int* in_sizes, int n_in,
                              void* d_out, int out_size)
{
    const float* query = (const float*)d_in[0];
    const float* in_w  = (const float*)d_in[3];
    const float* in_b  = (const float*)d_in[4];
    const float* out_w = (const float*)d_in[5];
    const float* out_b = (const float*)d_in[6];
    float* out = (float*)d_out;

    __nv_bfloat16 *xhi, *xlo, *whi, *wlo, *owhi, *owlo, *ahi, *alo;
    cudaGetSymbolAddress((void**)&xhi,  g_Xhi);  cudaGetSymbolAddress((void**)&xlo,  g_Xlo);
    cudaGetSymbolAddress((void**)&whi,  g_Whi);  cudaGetSymbolAddress((void**)&wlo,  g_Wlo);
    cudaGetSymbolAddress((void**)&owhi, g_OWhi); cudaGetSymbolAddress((void**)&owlo, g_OWlo);
    cudaGetSymbolAddress((void**)&ahi,  g_Ahi);  cudaGetSymbolAddress((void**)&alo,  g_Alo);

    // 0) fp32 -> bf16 hi/lo splits
    cvt_split_kernel<<<(TB * E_DIM / 4 + 255) / 256, 256>>>(query, xhi, xlo, TB * E_DIM / 4);
    cvt_split_kernel<<<(E3 * E_DIM / 4 + 255) / 256, 256>>>(in_w, whi, wlo, E3 * E_DIM / 4);
    cvt_split_kernel<<<(E_DIM * E_DIM / 4 + 255) / 256, 256>>>(out_w, owhi, owlo, E_DIM * E_DIM / 4);

    // 1) QKV projection via HMMA (exact R6)
    hmma_gemm_kernel<0><<<dim3(E3 / 128, TB / 128), 256>>>(xhi, xlo, whi, wlo, in_b, nullptr);

    // 2) HMMA flash attention (R6 + V-staging fix only)
    cudaFuncSetAttribute(flash_hmma_kernel,
                         cudaFuncAttributeMaxDynamicSharedMemorySize, FSMEM);
    flash_hmma_kernel<<<dim3(B_DIM * H_DIM, T_DIM / 64), 128, FSMEM>>>();

    // 3) Output projection via HMMA (exact R6)
    hmma_gemm_kernel<1><<<dim3(E_DIM / 128, TB / 128), 256>>>(ahi, alo, owhi, owlo, out_b, out);
}

// round 10
// speedup vs baseline: 2.3887x; 1.1522x over previous
#include <cuda_runtime.h>
#include <cuda_bf16.h>
#include <cstdint>

// Problem constants
#define T_DIM 2048
#define B_DIM 2
#define E_DIM 1024
#define H_DIM 16
#define DH    64
#define TB    (T_DIM * B_DIM)   // 4096
#define E3    (3 * E_DIM)       // 3072

// ---------------------------------------------------------------------------
// Device scratch (no runtime allocation allowed)
// ---------------------------------------------------------------------------
__device__ float g_Q[B_DIM * H_DIM * T_DIM * DH];   // [B*H][T][DH], pre-scaled
__device__ float g_K[B_DIM * H_DIM * T_DIM * DH];
__device__ float g_V[B_DIM * H_DIM * T_DIM * DH];

__device__ __nv_bfloat16 g_Xhi[TB * E_DIM],  g_Xlo[TB * E_DIM];        // query split
__device__ __nv_bfloat16 g_Whi[E3 * E_DIM],  g_Wlo[E3 * E_DIM];        // in_proj_weight split
__device__ __nv_bfloat16 g_OWhi[E_DIM * E_DIM], g_OWlo[E_DIM * E_DIM]; // out_w split
__device__ __nv_bfloat16 g_Ahi[TB * E_DIM],  g_Alo[TB * E_DIM];        // attn output split

// ---------------------------------------------------------------------------
// Helpers (R3/R6/R9-proven)
// ---------------------------------------------------------------------------
__device__ __forceinline__ uint32_t smem_u32(const void* p) {
    uint32_t a;
    asm("{ .reg .u64 t; cvta.to.shared.u64 t, %1; cvt.u32.u64 %0, t; }" : "=r"(a) : "l"(p));
    return a;
}

__device__ __forceinline__ void ldsm_x4(uint32_t& r0, uint32_t& r1, uint32_t& r2,
                                        uint32_t& r3, uint32_t addr) {
    asm volatile("ldmatrix.sync.aligned.m8n8.x4.shared.b16 {%0,%1,%2,%3}, [%4];"
                 : "=r"(r0), "=r"(r1), "=r"(r2), "=r"(r3) : "r"(addr));
}

__device__ __forceinline__ void mma_bf16(float* d, const uint32_t* a, const uint32_t* b) {
    asm volatile(
        "mma.sync.aligned.m16n8k16.row.col.f32.bf16.bf16.f32 "
        "{%0,%1,%2,%3}, {%4,%5,%6,%7}, {%8,%9}, {%0,%1,%2,%3};"
        : "+f"(d[0]), "+f"(d[1]), "+f"(d[2]), "+f"(d[3])
        : "r"(a[0]), "r"(a[1]), "r"(a[2]), "r"(a[3]), "r"(b[0]), "r"(b[1]));
}

// Scalar hi/lo packing (proven in R3/R6)
__device__ __forceinline__ uint32_t pack2(float a, float b) {
    __nv_bfloat162 p(__float2bfloat16(a), __float2bfloat16(b));
    return *reinterpret_cast<uint32_t*>(&p);
}
__device__ __forceinline__ uint32_t pack_hi2(float a, float b, float& ra, float& rb) {
    __nv_bfloat16 ha = __float2bfloat16(a), hb = __float2bfloat16(b);
    ra = a - __bfloat162float(ha);
    rb = b - __bfloat162float(hb);
    __nv_bfloat162 p(ha, hb);
    return *reinterpret_cast<uint32_t*>(&p);
}

// ---------------------------------------------------------------------------
// Kernel 0: fp32 -> (bf16 hi, bf16 lo) split conversion (EXACT R3/R6 version)
// ---------------------------------------------------------------------------
__global__ __launch_bounds__(256) void cvt_split_kernel(
    const float* __restrict__ x, __nv_bfloat16* __restrict__ hi,
    __nv_bfloat16* __restrict__ lo, int n4)
{
    int i = blockIdx.x * blockDim.x + threadIdx.x;
    if (i >= n4) return;
    float4 v = reinterpret_cast<const float4*>(x)[i];
    __nv_bfloat16 h0 = __float2bfloat16(v.x), h1 = __float2bfloat16(v.y);
    __nv_bfloat16 h2 = __float2bfloat16(v.z), h3 = __float2bfloat16(v.w);
    __nv_bfloat16 l0 = __float2bfloat16(v.x - __bfloat162float(h0));
    __nv_bfloat16 l1 = __float2bfloat16(v.y - __bfloat162float(h1));
    __nv_bfloat16 l2 = __float2bfloat16(v.z - __bfloat162float(h2));
    __nv_bfloat16 l3 = __float2bfloat16(v.w - __bfloat162float(h3));
    __nv_bfloat162* hp = reinterpret_cast<__nv_bfloat162*>(hi);
    __nv_bfloat162* lp = reinterpret_cast<__nv_bfloat162*>(lo);
    hp[2 * i + 0] = __nv_bfloat162(h0, h1);
    hp[2 * i + 1] = __nv_bfloat162(h2, h3);
    lp[2 * i + 0] = __nv_bfloat162(l0, l1);
    lp[2 * i + 1] = __nv_bfloat162(l2, l3);
}

// ---------------------------------------------------------------------------
// HMMA split-bf16 GEMM — EXACT R6/R9 logic; ONLY change: __launch_bounds__
// min-blocks=2 so two CTAs co-reside per SM (cross-CTA load/MMA overlap).
// MODE 0: QKV -> scatter fp32 g_Q (*0.125), g_K, g_V.  MODE 1: out-proj.
// ---------------------------------------------------------------------------
#define BK     32
#define PITCH  80
#define BUFSZ  (128 * PITCH)   // 10240

template<int MODE>
__global__ __launch_bounds__(256, 2) void hmma_gemm_kernel(
    const __nv_bfloat16* __restrict__ Ahi, const __nv_bfloat16* __restrict__ Alo,
    const __nv_bfloat16* __restrict__ Bhi, const __nv_bfloat16* __restrict__ Blo,
    const float* __restrict__ bias, float* __restrict__ out)
{
    __shared__ char smem[4 * BUFSZ];
    char* sAh = smem;
    char* sAl = smem + BUFSZ;
    char* sBh = smem + 2 * BUFSZ;
    char* sBl = smem + 3 * BUFSZ;

    const int tid  = threadIdx.x;
    const int wid  = tid >> 5;
    const int lane = tid & 31;
    const int wm = wid & 3;
    const int wn = wid >> 2;
    const int rowBase = blockIdx.y * 128;
    const int colBase = blockIdx.x * 128;

    const uint32_t sb_Ah = smem_u32(sAh);
    const uint32_t sb_Al = smem_u32(sAl);
    const uint32_t sb_Bh = smem_u32(sBh);
    const uint32_t sb_Bl = smem_u32(sBl);

    float acc[2][8][4];
#pragma unroll
    for (int i = 0; i < 2; i++)
#pragma unroll
        for (int j = 0; j < 8; j++)
#pragma unroll
            for (int k = 0; k < 4; k++) acc[i][j][k] = 0.0f;

    const uint32_t aoff = (uint32_t)((wm * 32 + (lane & 15)) * PITCH + (lane >> 4) * 16);
    const uint32_t boff = (uint32_t)((wn * 64 + (lane >> 4) * 8 + (lane & 7)) * PITCH +
                                     ((lane >> 3) & 1) * 16);

    for (int k0 = 0; k0 < E_DIM; k0 += BK) {
        __syncthreads();
#pragma unroll
        for (int s = 0; s < 2; s++) {
            int unit = tid + s * 256;
            int row = unit >> 2, seg = unit & 3;
            uint32_t so = (uint32_t)(row * PITCH + seg * 16);
            size_t ao = (size_t)(rowBase + row) * E_DIM + k0 + seg * 8;
            size_t bo = (size_t)(colBase + row) * E_DIM + k0 + seg * 8;
            *reinterpret_cast<uint4*>(sAh + so) = *reinterpret_cast<const uint4*>(Ahi + ao);
            *reinterpret_cast<uint4*>(sAl + so) = *reinterpret_cast<const uint4*>(Alo + ao);
            *reinterpret_cast<uint4*>(sBh + so) = *reinterpret_cast<const uint4*>(Bhi + bo);
            *reinterpret_cast<uint4*>(sBl + so) = *reinterpret_cast<const uint4*>(Blo + bo);
        }
        __syncthreads();

#pragma unroll
        for (int ks = 0; ks < BK; ks += 16) {
            const uint32_t kb = (uint32_t)(ks * 2);
            uint32_t ah[2][4], al[2][4];
#pragma unroll
            for (int mt = 0; mt < 2; mt++) {
                uint32_t ar = aoff + (uint32_t)(mt * 16 * PITCH) + kb;
                ldsm_x4(ah[mt][0], ah[mt][1], ah[mt][2], ah[mt][3], sb_Ah + ar);
                ldsm_x4(al[mt][0], al[mt][1], al[mt][2], al[mt][3], sb_Al + ar);
            }
#pragma unroll
            for (int np = 0; np < 4; np++) {
                uint32_t br = boff + (uint32_t)(np * 16 * PITCH) + kb;
                uint32_t bh[4], bl[4];
                ldsm_x4(bh[0], bh[1], bh[2], bh[3], sb_Bh + br);
                ldsm_x4(bl[0], bl[1], bl[2], bl[3], sb_Bl + br);
#pragma unroll
                for (int mt = 0; mt < 2; mt++) {
#pragma unroll
                    for (int j = 0; j < 2; j++) {
                        float* d = acc[mt][np * 2 + j];
                        mma_bf16(d, ah[mt], &bh[j * 2]);
                        mma_bf16(d, ah[mt], &bl[j * 2]);
                        mma_bf16(d, al[mt], &bh[j * 2]);
                    }
                }
            }
        }
    }

    const int rloc = wm * 32 + (lane >> 2);
    const int cloc = wn * 64 + (lane & 3) * 2;

    if (MODE == 0) {
        const int f0 = colBase + wn * 64;
        const int which = f0 >> 10;
        const int h = (f0 & 1023) >> 6;
        float* base;
        float scale;
        if (which == 0)      { base = g_Q; scale = 0.125f; }
        else if (which == 1) { base = g_K; scale = 1.0f; }
        else                 { base = g_V; scale = 1.0f; }
#pragma unroll
        for (int mt = 0; mt < 2; mt++) {
#pragma unroll
            for (int half = 0; half < 2; half++) {
                int r = rowBase + rloc + mt * 16 + half * 8;
                int t = r >> 1, bb = r & 1;
                float* dst = base + ((size_t)(bb * H_DIM + h) * T_DIM + t) * DH;
#pragma unroll
                for (int nt = 0; nt < 8; nt++) {
                    int d = (nt * 8) + (cloc & 63);
                    float2 v;
                    v.x = (acc[mt][nt][half * 2 + 0] + bias[f0 + d])     * scale;
                    v.y = (acc[mt][nt][half * 2 + 1] + bias[f0 + d + 1]) * scale;
                    *reinterpret_cast<float2*>(dst + d) = v;
                }
            }
        }
    } else {
#pragma unroll
        for (int mt = 0; mt < 2; mt++) {
#pragma unroll
            for (int half = 0; half < 2; half++) {
                int r = rowBase + rloc + mt * 16 + half * 8;
                float* dst = out + (size_t)r * E_DIM;
#pragma unroll
                for (int nt = 0; nt < 8; nt++) {
                    int c = colBase + wn * 64 + nt * 8 + (lane & 3) * 2;
                    float2 v;
                    v.x = acc[mt][nt][half * 2 + 0] + bias[c];
                    v.y = acc[mt][nt][half * 2 + 1] + bias[c + 1];
                    *reinterpret_cast<float2*>(dst + c) = v;
                }
            }
        }
    }
}

// ---------------------------------------------------------------------------
// Kernel 2: HMMA flash attention — EXACT R9 (passing) kernel, unchanged.
// ---------------------------------------------------------------------------
#define FPITCH 72
#define FPB    (FPITCH * 2)          // 144 bytes/row
#define FBUF   (64 * FPB)            // 9216 bytes
#define FSMEM  (6 * FBUF)            // 55296 bytes

__global__ __launch_bounds__(128) void flash_hmma_kernel()
{
    extern __shared__ char fsm[];
    char* sQh = fsm;
    char* sQl = fsm + FBUF;
    char* sKh = fsm + 2 * FBUF;      // reused for P-hi after S stage
    char* sKl = fsm + 3 * FBUF;      // reused for P-lo
    char* sVt = fsm + 4 * FBUF;
    char* sVl = fsm + 5 * FBUF;

    const int tid = threadIdx.x;
    const int lane = tid & 31;
    const int w = tid >> 5;
    const int bh = blockIdx.x;
    const int q0 = blockIdx.y * 64;

    const size_t hbase = (size_t)bh * T_DIM * DH;
    const float* Qg = g_Q + hbase;
    const float* Kg = g_K + hbase;
    const float* Vg = g_V + hbase;

    // Stage Q tile: fp32 -> hi/lo bf16, rows = q
#pragma unroll
    for (int s = 0; s < 8; s++) {
        int unit = tid + s * 128;            // 0..1023
        int row = unit >> 4;                 // 0..63
        int c4 = (unit & 15) * 4;            // 0..60
        float4 q = *reinterpret_cast<const float4*>(Qg + (q0 + row) * DH + c4);
        float r0, r1, r2, r3;
        uint32_t h01 = pack_hi2(q.x, q.y, r0, r1);
        uint32_t h23 = pack_hi2(q.z, q.w, r2, r3);
        uint32_t so = (uint32_t)(row * FPB + c4 * 2);
        *reinterpret_cast<uint2*>(sQh + so) = make_uint2(h01, h23);
        *reinterpret_cast<uint2*>(sQl + so) = make_uint2(pack2(r0, r1), pack2(r2, r3));
    }
    __syncthreads();

    // Persistent Q A-fragments
    uint32_t aqh[4][4], aql[4][4];
    const uint32_t qaddr = smem_u32(sQh) +
        (uint32_t)((w * 16 + (lane & 15)) * FPB + (lane >> 4) * 16);
#pragma unroll
    for (int ks = 0; ks < 4; ks++) {
        ldsm_x4(aqh[ks][0], aqh[ks][1], aqh[ks][2], aqh[ks][3], qaddr + ks * 32);
        ldsm_x4(aql[ks][0], aql[ks][1], aql[ks][2], aql[ks][3], qaddr + FBUF + ks * 32);
    }

    float o[8][4];
#pragma unroll
    for (int i = 0; i < 8; i++)
#pragma unroll
        for (int j = 0; j < 4; j++) o[i][j] = 0.0f;
    float m1 = -1e30f, m2 = -1e30f, l1 = 0.0f, l2 = 0.0f;

    const uint32_t blanes = (uint32_t)(((lane >> 4) * 8 + (lane & 7)) * FPB +
                                       ((lane >> 3) & 1) * 16);
    const uint32_t kaddr = smem_u32(sKh) + blanes;
    const uint32_t vaddr = smem_u32(sVt) + blanes;
    const uint32_t paddr = smem_u32(sKh) +
        (uint32_t)((w * 16 + (lane & 15)) * FPB + (lane >> 4) * 16);

    const int r1loc = w * 16 + (lane >> 2);
    const int r2loc = r1loc + 8;

    for (int kt = 0; kt < T_DIM; kt += 64) {
        __syncthreads();   // previous iteration's P/V reads complete
        // Stage K (rows=key, cols=d)
#pragma unroll
        for (int s = 0; s < 8; s++) {
            int unit = tid + s * 128;
            int row = unit >> 4;             // key row 0..63
            int c4 = (unit & 15) * 4;        // d 0..60
            float4 kf = *reinterpret_cast<const float4*>(Kg + (kt + row) * DH + c4);
            float r0, r1, r2, r3;
            uint32_t h01 = pack_hi2(kf.x, kf.y, r0, r1);
            uint32_t h23 = pack_hi2(kf.z, kf.w, r2, r3);
            uint32_t so = (uint32_t)(row * FPB + c4 * 2);
            *reinterpret_cast<uint2*>(sKh + so) = make_uint2(h01, h23);
            *reinterpret_cast<uint2*>(sKl + so) = make_uint2(pack2(r0, r1), pack2(r2, r3));
        }
        // Stage V transposed (rows=d, cols=key): (d, 4-key chunk) mapping
#pragma unroll
        for (int s = 0; s < 8; s++) {
            int unit = tid + s * 128;        // 0..1023
            int d = unit & 63;               // Vt row
            int kc = (unit >> 6) * 4;        // key base 0..60
            float v0 = Vg[(kt + kc + 0) * DH + d];
            float v1 = Vg[(kt + kc + 1) * DH + d];
            float v2 = Vg[(kt + kc + 2) * DH + d];
            float v3 = Vg[(kt + kc + 3) * DH + d];
            float r0, r1, r2, r3;
            uint32_t h01 = pack_hi2(v0, v1, r0, r1);
            uint32_t h23 = pack_hi2(v2, v3, r2, r3);
            uint32_t vo = (uint32_t)(d * FPB + kc * 2);
            *reinterpret_cast<uint2*>(sVt + vo) = make_uint2(h01, h23);
            *reinterpret_cast<uint2*>(sVl + vo) = make_uint2(pack2(r0, r1), pack2(r2, r3));
        }
        __syncthreads();

        // S = Q K^T (warp: 16 q-rows x 64 keys)
        float s4[8][4];
#pragma unroll
        for (int i = 0; i < 8; i++)
#pragma unroll
            for (int j = 0; j < 4; j++) s4[i][j] = 0.0f;

#pragma unroll
        for (int ks = 0; ks < 4; ks++) {
#pragma unroll
            for (int np = 0; np < 4; np++) {
                uint32_t ba = kaddr + (uint32_t)(np * 16 * FPB) + ks * 32;
                uint32_t bh[4], bl[4];
                ldsm_x4(bh[0], bh[1], bh[2], bh[3], ba);
                ldsm_x4(bl[0], bl[1], bl[2], bl[3], ba + FBUF);
#pragma unroll
                for (int j = 0; j < 2; j++) {
                    float* d = s4[np * 2 + j];
                    mma_bf16(d, aqh[ks], &bh[j * 2]);
                    mma_bf16(d, aqh[ks], &bl[j * 2]);
                    mma_bf16(d, aql[ks], &bh[j * 2]);
                }
            }
        }

        // Online softmax
        float mx1 = -1e30f, mx2 = -1e30f;
#pragma unroll
        for (int nt = 0; nt < 8; nt++) {
            mx1 = fmaxf(mx1, fmaxf(s4[nt][0], s4[nt][1]));
            mx2 = fmaxf(mx2, fmaxf(s4[nt][2], s4[nt][3]));
        }
        mx1 = fmaxf(mx1, __shfl_xor_sync(0xffffffffu, mx1, 1));
        mx1 = fmaxf(mx1, __shfl_xor_sync(0xffffffffu, mx1, 2));
        mx2 = fmaxf(mx2, __shfl_xor_sync(0xffffffffu, mx2, 1));
        mx2 = fmaxf(mx2, __shfl_xor_sync(0xffffffffu, mx2, 2));

        float mn1 = fmaxf(m1, mx1), mn2 = fmaxf(m2, mx2);
        float c1 = __expf(m1 - mn1), c2 = __expf(m2 - mn2);
        m1 = mn1; m2 = mn2;

        float p1 = 0.0f, p2 = 0.0f;
#pragma unroll
        for (int nt = 0; nt < 8; nt++) {
            s4[nt][0] = __expf(s4[nt][0] - mn1); p1 += s4[nt][0];
            s4[nt][1] = __expf(s4[nt][1] - mn1); p1 += s4[nt][1];
            s4[nt][2] = __expf(s4[nt][2] - mn2); p2 += s4[nt][2];
            s4[nt][3] = __expf(s4[nt][3] - mn2); p2 += s4[nt][3];
        }
        l1 = l1 * c1 + p1;
        l2 = l2 * c2 + p2;
#pragma unroll
        for (int nt = 0; nt < 8; nt++) {
            o[nt][0] *= c1; o[nt][1] *= c1;
            o[nt][2] *= c2; o[nt][3] *= c2;
        }

        __syncthreads();   // all warps finished reading K before P overwrites it
#pragma unroll
        for (int nt = 0; nt < 8; nt++) {
            int col = nt * 8 + (lane & 3) * 2;
            float ra, rb;
            uint32_t ph = pack_hi2(s4[nt][0], s4[nt][1], ra, rb);
            uint32_t so1 = (uint32_t)(r1loc * FPB + col * 2);
            *reinterpret_cast<uint32_t*>(sKh + so1) = ph;
            *reinterpret_cast<uint32_t*>(sKl + so1) = pack2(ra, rb);
            ph = pack_hi2(s4[nt][2], s4[nt][3], ra, rb);
            uint32_t so2 = (uint32_t)(r2loc * FPB + col * 2);
            *reinterpret_cast<uint32_t*>(sKh + so2) = ph;
            *reinterpret_cast<uint32_t*>(sKl + so2) = pack2(ra, rb);
        }
        __syncwarp();      // warp reads only its own 16 P rows

        // O += P V
#pragma unroll
        for (int ks = 0; ks < 4; ks++) {
            uint32_t pah[4], pal[4];
            ldsm_x4(pah[0], pah[1], pah[2], pah[3], paddr + ks * 32);
            ldsm_x4(pal[0], pal[1], pal[2], pal[3], paddr + FBUF + ks * 32);
#pragma unroll
            for (int np = 0; np < 4; np++) {
                uint32_t ba = vaddr + (uint32_t)(np * 16 * FPB) + ks * 32;
                uint32_t bvh[4], bvl[4];
                ldsm_x4(bvh[0], bvh[1], bvh[2], bvh[3], ba);
                ldsm_x4(bvl[0], bvl[1], bvl[2], bvl[3], ba + FBUF);
#pragma unroll
                for (int j = 0; j < 2; j++) {
                    float* d = o[np * 2 + j];
                    mma_bf16(d, pah, &bvh[j * 2]);
                    mma_bf16(d, pah, &bvl[j * 2]);
                    mma_bf16(d, pal, &bvh[j * 2]);
                }
            }
        }
    }

    // Epilogue: normalize, write bf16 hi/lo to g_Ahi/g_Alo [t*B+b][h*DH+d]
    l1 += __shfl_xor_sync(0xffffffffu, l1, 1);
    l1 += __shfl_xor_sync(0xffffffffu, l1, 2);
    l2 += __shfl_xor_sync(0xffffffffu, l2, 1);
    l2 += __shfl_xor_sync(0xffffffffu, l2, 2);
    const float inv1 = 1.0f / l1, inv2 = 1.0f / l2;

    const int r1 = q0 + r1loc;
    const int r2 = q0 + r2loc;
    const int b = bh >> 4;
    const int h = bh & 15;

#pragma unroll
    for (int nt = 0; nt < 8; nt++) {
        int d = nt * 8 + (lane & 3) * 2;
        float ra, rb;
        uint32_t hh = pack_hi2(o[nt][0] * inv1, o[nt][1] * inv1, ra, rb);
        size_t i1 = ((size_t)r1 * B_DIM + b) * E_DIM + h * DH + d;
        *reinterpret_cast<uint32_t*>(&g_Ahi[i1]) = hh;
        *reinterpret_cast<uint32_t*>(&g_Alo[i1]) = pack2(ra, rb);
        hh = pack_hi2(o[nt][2] * inv2, o[nt][3] * inv2, ra, rb);
        size_t i2 = ((size_t)r2 * B_DIM + b) * E_DIM + h * DH + d;
        *reinterpret_cast<uint32_t*>(&g_Ahi[i2]) = hh;
        *reinterpret_cast<uint32_t*>(&g_Alo[i2]) = pack2(ra, rb);
    }
}

// ---------------------------------------------------------------------------
// Launch
// ---------------------------------------------------------------------------
extern "C" void kernel_launch(void* const* d_in, const int* in_sizes, int n_in,
                              void* d_out, int out_size)
{
    const float* query = (const float*)d_in[0];
    const float* in_w  = (const float*)d_in[3];
    const float* in_b  = (const float*)d_in[4];
    const float* out_w = (const float*)d_in[5];
    const float* out_b = (const float*)d_in[6];
    float* out = (float*)d_out;

    __nv_bfloat16 *xhi, *xlo, *whi, *wlo, *owhi, *owlo, *ahi, *alo;
    cudaGetSymbolAddress((void**)&xhi,  g_Xhi);  cudaGetSymbolAddress((void**)&xlo,  g_Xlo);
    cudaGetSymbolAddress((void**)&whi,  g_Whi);  cudaGetSymbolAddress((void**)&wlo,  g_Wlo);
    cudaGetSymbolAddress((void**)&owhi, g_OWhi); cudaGetSymbolAddress((void**)&owlo, g_OWlo);
    cudaGetSymbolAddress((void**)&ahi,  g_Ahi);  cudaGetSymbolAddress((void**)&alo,  g_Alo);

    // 0) fp32 -> bf16 hi/lo splits
    cvt_split_kernel<<<(TB * E_DIM / 4 + 255) / 256, 256>>>(query, xhi, xlo, TB * E_DIM / 4);
    cvt_split_kernel<<<(E3 * E_DIM / 4 + 255) / 256, 256>>>(in_w, whi, wlo, E3 * E_DIM / 4);
    cvt_split_kernel<<<(E_DIM * E_DIM / 4 + 255) / 256, 256>>>(out_w, owhi, owlo, E_DIM * E_DIM / 4);

    // 1) QKV projection via HMMA (2 CTAs/SM)
    hmma_gemm_kernel<0><<<dim3(E3 / 128, TB / 128), 256>>>(xhi, xlo, whi, wlo, in_b, nullptr);

    // 2) HMMA flash attention (exact R9)
    cudaFuncSetAttribute(flash_hmma_kernel,
                         cudaFuncAttributeMaxDynamicSharedMemorySize, FSMEM);
    flash_hmma_kernel<<<dim3(B_DIM * H_DIM, T_DIM / 64), 128, FSMEM>>>();

    // 3) Output projection via HMMA (2 CTAs/SM)
    hmma_gemm_kernel<1><<<dim3(E_DIM / 128, TB / 128), 256>>>(ahi, alo, owhi, owlo, out_b, out);
}